// round 1
// baseline (speedup 1.0000x reference)
#include <cuda_runtime.h>
#include <math.h>

// Problem dims (fixed by reference): B=2, N=2048, C=1024, H=16, D=64, FF=4096
#define MTOT 4096      // B*N
#define CDIM 1024
#define FFDIM 4096
#define NSEQ 2048
#define NHEAD 16
#define HDIM 64

// ---------------- scratch (no allocations allowed -> __device__ globals) ----
__device__ float g_xn [MTOT * CDIM];
__device__ float g_q  [MTOT * CDIM];
__device__ float g_k  [MTOT * CDIM];
__device__ float g_v  [MTOT * CDIM];
__device__ float g_ctx[MTOT * CDIM];
__device__ float g_x2 [MTOT * CDIM];
__device__ float g_xn2[MTOT * CDIM];
__device__ float g_h  [MTOT * FFDIM];

// ---------------- RMSNorm ---------------------------------------------------
// norm = sqrt(sum x^2); rms = norm/sqrt(C); out = scale * x / (rms + 1e-8)
__global__ __launch_bounds__(256) void rmsnorm_kernel(
    const float* __restrict__ x, const float* __restrict__ scale,
    float* __restrict__ out)
{
    __shared__ float red[8];
    const int row = blockIdx.x;
    const int t   = threadIdx.x;
    const float* xr = x + (size_t)row * CDIM;

    float4 v = *reinterpret_cast<const float4*>(xr + t * 4);
    float ss = v.x * v.x + v.y * v.y + v.z * v.z + v.w * v.w;
    #pragma unroll
    for (int o = 16; o > 0; o >>= 1) ss += __shfl_xor_sync(0xffffffffu, ss, o);
    if ((t & 31) == 0) red[t >> 5] = ss;
    __syncthreads();
    if (t < 8) {
        float s2 = red[t];
        #pragma unroll
        for (int o = 4; o > 0; o >>= 1) s2 += __shfl_xor_sync(0xffu, s2, o);
        if (t == 0) red[0] = s2;
    }
    __syncthreads();
    const float norm = sqrtf(red[0]);
    const float inv  = 1.0f / (norm * 0.03125f + 1e-8f);   // 1/sqrt(1024)=0.03125

    float4 sc = *reinterpret_cast<const float4*>(scale + t * 4);
    float4 o4;
    o4.x = v.x * sc.x * inv; o4.y = v.y * sc.y * inv;
    o4.z = v.z * sc.z * inv; o4.w = v.w * sc.w * inv;
    *reinterpret_cast<float4*>(out + (size_t)row * CDIM + t * 4) = o4;
}

// ---------------- rotary: y[d] = x[d] - x[(d-1) mod 64] per head row --------
__global__ __launch_bounds__(256) void rotary_kernel(float* __restrict__ p)
{
    const int idx = blockIdx.x * blockDim.x + threadIdx.x;   // 0 .. MTOT*NHEAD-1
    float* r = p + (size_t)idx * HDIM;
    float v[HDIM];
    #pragma unroll
    for (int i = 0; i < HDIM / 4; i++) {
        float4 q4 = *reinterpret_cast<const float4*>(r + i * 4);
        v[i*4+0] = q4.x; v[i*4+1] = q4.y; v[i*4+2] = q4.z; v[i*4+3] = q4.w;
    }
    #pragma unroll
    for (int i = 0; i < HDIM / 4; i++) {
        float4 o4;
        o4.x = v[i*4+0] - v[(i*4+0 + HDIM-1) & (HDIM-1)];
        o4.y = v[i*4+1] - v[i*4+0];
        o4.z = v[i*4+2] - v[i*4+1];
        o4.w = v[i*4+3] - v[i*4+2];
        *reinterpret_cast<float4*>(r + i * 4) = o4;
    }
}

// ---------------- SGEMM 128x128x8, 8x8/thread, epilogues --------------------
// EPI: 0 = bias only; 1 = bias + residual; 2 = bias + exact GELU
__device__ __forceinline__ float gelu_exact(float x) {
    return 0.5f * x * (1.0f + erff(x * 0.7071067811865476f));
}

template <int EPI>
__global__ __launch_bounds__(256) void sgemm_kernel(
    const float* __restrict__ A, const float* __restrict__ Bw,
    const float* __restrict__ bias, const float* __restrict__ res,
    float* __restrict__ Cc, int M, int Nn, int K)
{
    constexpr int BM = 128, BN = 128, BK = 8, TM = 8, TN = 8;
    __shared__ float As[BK][BM];
    __shared__ float Bs[BK][BN];

    const int t  = threadIdx.x;
    const int bm = blockIdx.y * BM;
    const int bn = blockIdx.x * BN;

    const int aRow  = t >> 1;            // 0..127
    const int aCol4 = (t & 1) * 4;       // 0 or 4
    const int bRow  = t >> 5;            // 0..7
    const int bCol4 = (t & 31) * 4;      // 0..124

    const int tx = t & 15;               // 0..15 -> col group
    const int ty = t >> 4;               // 0..15 -> row group

    float acc[TM][TN];
    #pragma unroll
    for (int i = 0; i < TM; i++)
        #pragma unroll
        for (int j = 0; j < TN; j++) acc[i][j] = 0.0f;

    for (int k0 = 0; k0 < K; k0 += BK) {
        float4 av = *reinterpret_cast<const float4*>(
            &A[(size_t)(bm + aRow) * K + k0 + aCol4]);
        As[aCol4 + 0][aRow] = av.x;
        As[aCol4 + 1][aRow] = av.y;
        As[aCol4 + 2][aRow] = av.z;
        As[aCol4 + 3][aRow] = av.w;
        float4 bv = *reinterpret_cast<const float4*>(
            &Bw[(size_t)(k0 + bRow) * Nn + bn + bCol4]);
        *reinterpret_cast<float4*>(&Bs[bRow][bCol4]) = bv;
        __syncthreads();

        #pragma unroll
        for (int k = 0; k < BK; k++) {
            float ar[TM], br[TN];
            #pragma unroll
            for (int i = 0; i < TM; i++) ar[i] = As[k][ty * TM + i];
            #pragma unroll
            for (int j = 0; j < TN; j++) br[j] = Bs[k][tx * TN + j];
            #pragma unroll
            for (int i = 0; i < TM; i++)
                #pragma unroll
                for (int j = 0; j < TN; j++)
                    acc[i][j] = fmaf(ar[i], br[j], acc[i][j]);
        }
        __syncthreads();
    }

    #pragma unroll
    for (int i = 0; i < TM; i++) {
        const int row = bm + ty * TM + i;
        #pragma unroll
        for (int j4 = 0; j4 < 2; j4++) {
            const int col = bn + tx * TN + j4 * 4;
            float4 bi = *reinterpret_cast<const float4*>(bias + col);
            float4 c;
            c.x = acc[i][j4*4+0] + bi.x;
            c.y = acc[i][j4*4+1] + bi.y;
            c.z = acc[i][j4*4+2] + bi.z;
            c.w = acc[i][j4*4+3] + bi.w;
            if (EPI == 1) {
                float4 r4 = *reinterpret_cast<const float4*>(
                    res + (size_t)row * Nn + col);
                c.x += r4.x; c.y += r4.y; c.z += r4.z; c.w += r4.w;
            } else if (EPI == 2) {
                c.x = gelu_exact(c.x); c.y = gelu_exact(c.y);
                c.z = gelu_exact(c.z); c.w = gelu_exact(c.w);
            }
            *reinterpret_cast<float4*>(Cc + (size_t)row * Nn + col) = c;
        }
    }
}

// ---------------- Flash attention (no mask), D=64, online softmax -----------
// grid.x = NSEQ/128, grid.y = B*H.  One query row per thread.
__global__ __launch_bounds__(128) void flash_attn_kernel(
    const float* __restrict__ q, const float* __restrict__ k,
    const float* __restrict__ v, float* __restrict__ o)
{
    constexpr int BKV = 32;
    __shared__ float Ks[BKV][HDIM];
    __shared__ float Vs[BKV][HDIM];
    __shared__ float Ss[128][BKV + 1];

    const int t = threadIdx.x;
    const int b = blockIdx.y >> 4;
    const int h = blockIdx.y & 15;
    const int n = blockIdx.x * 128 + t;

    const size_t rowbase = ((size_t)(b * NSEQ + n)) * CDIM + h * HDIM;
    const size_t kvbase  = ((size_t)b * NSEQ) * CDIM + h * HDIM;

    float qr[HDIM];
    #pragma unroll
    for (int i = 0; i < HDIM / 4; i++) {
        float4 q4 = *reinterpret_cast<const float4*>(q + rowbase + i * 4);
        qr[i*4+0] = q4.x; qr[i*4+1] = q4.y; qr[i*4+2] = q4.z; qr[i*4+3] = q4.w;
    }

    float m = -1e30f, l = 0.0f;
    float acc[HDIM];
    #pragma unroll
    for (int d = 0; d < HDIM; d++) acc[d] = 0.0f;

    for (int kv0 = 0; kv0 < NSEQ; kv0 += BKV) {
        // load K/V tiles: BKV*HDIM = 2048 floats = 512 float4 each
        #pragma unroll
        for (int i = 0; i < 4; i++) {
            const int idx = i * 128 + t;          // 0..511
            const int j   = idx >> 4;             // 0..31
            const int d4  = (idx & 15) * 4;
            const size_t g = kvbase + (size_t)(kv0 + j) * CDIM + d4;
            *reinterpret_cast<float4*>(&Ks[j][d4]) =
                *reinterpret_cast<const float4*>(k + g);
            *reinterpret_cast<float4*>(&Vs[j][d4]) =
                *reinterpret_cast<const float4*>(v + g);
        }
        __syncthreads();

        float smax = -1e30f;
        for (int j = 0; j < BKV; j++) {
            float s = 0.0f;
            #pragma unroll
            for (int d = 0; d < HDIM; d++) s = fmaf(qr[d], Ks[j][d], s);
            s *= 0.125f;                          // 1/sqrt(64)
            Ss[t][j] = s;
            smax = fmaxf(smax, s);
        }
        const float mnew = fmaxf(m, smax);
        const float corr = __expf(m - mnew);
        l *= corr;
        #pragma unroll
        for (int d = 0; d < HDIM; d++) acc[d] *= corr;
        for (int j = 0; j < BKV; j++) {
            const float p = __expf(Ss[t][j] - mnew);
            l += p;
            #pragma unroll
            for (int d = 0; d < HDIM; d++) acc[d] = fmaf(p, Vs[j][d], acc[d]);
        }
        m = mnew;
        __syncthreads();
    }

    const float inv = 1.0f / l;
    #pragma unroll
    for (int i = 0; i < HDIM / 4; i++) {
        float4 o4;
        o4.x = acc[i*4+0] * inv; o4.y = acc[i*4+1] * inv;
        o4.z = acc[i*4+2] * inv; o4.w = acc[i*4+3] * inv;
        *reinterpret_cast<float4*>(o + rowbase + i * 4) = o4;
    }
}

// ---------------- host orchestration ----------------------------------------
extern "C" void kernel_launch(void* const* d_in, const int* in_sizes, int n_in,
                              void* d_out, int out_size)
{
    const float* x      = (const float*)d_in[0];
    const float* wq     = (const float*)d_in[1];
    const float* bq     = (const float*)d_in[2];
    const float* wk     = (const float*)d_in[3];
    const float* bk     = (const float*)d_in[4];
    const float* wv     = (const float*)d_in[5];
    const float* bv     = (const float*)d_in[6];
    const float* wo     = (const float*)d_in[7];
    const float* bo     = (const float*)d_in[8];
    const float* scale1 = (const float*)d_in[9];
    const float* scale2 = (const float*)d_in[10];
    const float* w1     = (const float*)d_in[11];
    const float* b1     = (const float*)d_in[12];
    const float* w2     = (const float*)d_in[13];
    const float* b2     = (const float*)d_in[14];
    float* out = (float*)d_out;

    float *p_xn, *p_q, *p_k, *p_v, *p_ctx, *p_x2, *p_xn2, *p_h;
    cudaGetSymbolAddress((void**)&p_xn,  g_xn);
    cudaGetSymbolAddress((void**)&p_q,   g_q);
    cudaGetSymbolAddress((void**)&p_k,   g_k);
    cudaGetSymbolAddress((void**)&p_v,   g_v);
    cudaGetSymbolAddress((void**)&p_ctx, g_ctx);
    cudaGetSymbolAddress((void**)&p_x2,  g_x2);
    cudaGetSymbolAddress((void**)&p_xn2, g_xn2);
    cudaGetSymbolAddress((void**)&p_h,   g_h);

    const dim3 gemm_cc(CDIM / 128, MTOT / 128);     // (8, 32)
    const dim3 gemm_cf(FFDIM / 128, MTOT / 128);    // (32, 32)

    // 1. xn = rms_norm(x, scale1)
    rmsnorm_kernel<<<MTOT, 256>>>(x, scale1, p_xn);

    // 2-4. q/k/v projections
    sgemm_kernel<0><<<gemm_cc, 256>>>(p_xn, wq, bq, nullptr, p_q, MTOT, CDIM, CDIM);
    sgemm_kernel<0><<<gemm_cc, 256>>>(p_xn, wk, bk, nullptr, p_k, MTOT, CDIM, CDIM);
    sgemm_kernel<0><<<gemm_cc, 256>>>(p_xn, wv, bv, nullptr, p_v, MTOT, CDIM, CDIM);

    // 5. rotary (q -= roll(q,1), k -= roll(k,1)) in place
    rotary_kernel<<<(MTOT * NHEAD) / 256, 256>>>(p_q);
    rotary_kernel<<<(MTOT * NHEAD) / 256, 256>>>(p_k);

    // 6. attention
    {
        dim3 grid(NSEQ / 128, 2 * NHEAD);
        flash_attn_kernel<<<grid, 128>>>(p_q, p_k, p_v, p_ctx);
    }

    // 7. x2 = x + ctx @ wo + bo
    sgemm_kernel<1><<<gemm_cc, 256>>>(p_ctx, wo, bo, x, p_x2, MTOT, CDIM, CDIM);

    // 8. xn2 = rms_norm(x2, scale2)
    rmsnorm_kernel<<<MTOT, 256>>>(p_x2, scale2, p_xn2);

    // 9. h = gelu(xn2 @ w1 + b1)
    sgemm_kernel<2><<<gemm_cf, 256>>>(p_xn2, w1, b1, nullptr, p_h, MTOT, FFDIM, CDIM);

    // 10. out = x2 + h @ w2 + b2
    sgemm_kernel<1><<<gemm_cc, 256>>>(p_h, w2, b2, p_x2, out, MTOT, CDIM, FFDIM);
}

// round 3
// speedup vs baseline: 1.5893x; 1.5893x over previous
#include <cuda_runtime.h>
#include <cuda_bf16.h>
#include <math.h>
#include <stdint.h>

// Problem dims (fixed): B=2, N=2048, C=1024, H=16, D=64, FF=4096
#define MTOT 4096      // B*N
#define CDIM 1024
#define FFDIM 4096
#define NSEQ 2048
#define NHEAD 16
#define HDIM 64

// ---------------- scratch (no allocations allowed -> __device__ globals) ----
__device__ float g_xn [MTOT * CDIM];
__device__ float g_q  [MTOT * CDIM];
__device__ float g_k  [MTOT * CDIM];
__device__ float g_v  [MTOT * CDIM];
__device__ float g_ctx[MTOT * CDIM];
__device__ float g_x2 [MTOT * CDIM];
__device__ float g_xn2[MTOT * CDIM];
__device__ float g_h  [MTOT * FFDIM];
// transposed weights [N,K]
__device__ float g_wqT[CDIM * CDIM];
__device__ float g_wkT[CDIM * CDIM];
__device__ float g_wvT[CDIM * CDIM];
__device__ float g_woT[CDIM * CDIM];
__device__ float g_w1T[CDIM * FFDIM];
__device__ float g_w2T[CDIM * FFDIM];

// ---------------- small helpers --------------------------------------------
__device__ __forceinline__ uint32_t smem_u32(const void* p) {
    uint32_t a;
    asm("{ .reg .u64 t; cvta.to.shared.u64 t, %1; cvt.u32.u64 %0, t; }"
        : "=r"(a) : "l"(p));
    return a;
}
__device__ __forceinline__ void ldmat4(uint32_t (&r)[4], uint32_t addr) {
    asm volatile("ldmatrix.sync.aligned.m8n8.x4.shared.b16 {%0,%1,%2,%3}, [%4];"
                 : "=r"(r[0]), "=r"(r[1]), "=r"(r[2]), "=r"(r[3]) : "r"(addr));
}
__device__ __forceinline__ void mma16816(float (&d)[4], const uint32_t (&a)[4],
                                         uint32_t b0, uint32_t b1) {
    asm volatile(
        "mma.sync.aligned.m16n8k16.row.col.f32.bf16.bf16.f32 "
        "{%0,%1,%2,%3}, {%4,%5,%6,%7}, {%8,%9}, {%0,%1,%2,%3};"
        : "+f"(d[0]), "+f"(d[1]), "+f"(d[2]), "+f"(d[3])
        : "r"(a[0]), "r"(a[1]), "r"(a[2]), "r"(a[3]), "r"(b0), "r"(b1));
}
__device__ __forceinline__ uint32_t pck(__nv_bfloat16 a, __nv_bfloat16 b) {
    __nv_bfloat162 t(a, b);
    return *reinterpret_cast<uint32_t*>(&t);
}
__device__ __forceinline__ float gelu_exact(float x) {
    return 0.5f * x * (1.0f + erff(x * 0.7071067811865476f));
}

// ---------------- RMSNorm ---------------------------------------------------
__global__ __launch_bounds__(256) void rmsnorm_kernel(
    const float* __restrict__ x, const float* __restrict__ scale,
    float* __restrict__ out)
{
    __shared__ float red[8];
    const int row = blockIdx.x;
    const int t   = threadIdx.x;
    const float* xr = x + (size_t)row * CDIM;

    float4 v = *reinterpret_cast<const float4*>(xr + t * 4);
    float ss = v.x * v.x + v.y * v.y + v.z * v.z + v.w * v.w;
    #pragma unroll
    for (int o = 16; o > 0; o >>= 1) ss += __shfl_xor_sync(0xffffffffu, ss, o);
    if ((t & 31) == 0) red[t >> 5] = ss;
    __syncthreads();
    if (t < 8) {
        float s2 = red[t];
        #pragma unroll
        for (int o = 4; o > 0; o >>= 1) s2 += __shfl_xor_sync(0xffu, s2, o);
        if (t == 0) red[0] = s2;
    }
    __syncthreads();
    const float norm = sqrtf(red[0]);
    const float inv  = 1.0f / (norm * 0.03125f + 1e-8f);

    float4 sc = *reinterpret_cast<const float4*>(scale + t * 4);
    float4 o4;
    o4.x = v.x * sc.x * inv; o4.y = v.y * sc.y * inv;
    o4.z = v.z * sc.z * inv; o4.w = v.w * sc.w * inv;
    *reinterpret_cast<float4*>(out + (size_t)row * CDIM + t * 4) = o4;
}

// ---------------- rotary ----------------------------------------------------
__global__ __launch_bounds__(256) void rotary_kernel(float* __restrict__ p)
{
    const int idx = blockIdx.x * blockDim.x + threadIdx.x;
    float* r = p + (size_t)idx * HDIM;
    float v[HDIM];
    #pragma unroll
    for (int i = 0; i < HDIM / 4; i++) {
        float4 q4 = *reinterpret_cast<const float4*>(r + i * 4);
        v[i*4+0] = q4.x; v[i*4+1] = q4.y; v[i*4+2] = q4.z; v[i*4+3] = q4.w;
    }
    #pragma unroll
    for (int i = 0; i < HDIM / 4; i++) {
        float4 o4;
        o4.x = v[i*4+0] - v[(i*4+0 + HDIM-1) & (HDIM-1)];
        o4.y = v[i*4+1] - v[i*4+0];
        o4.z = v[i*4+2] - v[i*4+1];
        o4.w = v[i*4+3] - v[i*4+2];
        *reinterpret_cast<float4*>(r + i * 4) = o4;
    }
}

// ---------------- weight transpose: out[c][r] = in[r][c] --------------------
__global__ __launch_bounds__(256) void transpose_kernel(
    const float* __restrict__ in, float* __restrict__ out, int R, int Cc)
{
    __shared__ float ts[32][33];
    const int tx = threadIdx.x, ty = threadIdx.y;
    const int c0 = blockIdx.x * 32, r0 = blockIdx.y * 32;
    #pragma unroll
    for (int i = 0; i < 4; i++)
        ts[ty + 8*i][tx] = in[(size_t)(r0 + ty + 8*i) * Cc + c0 + tx];
    __syncthreads();
    #pragma unroll
    for (int i = 0; i < 4; i++)
        out[(size_t)(c0 + ty + 8*i) * R + r0 + tx] = ts[tx][ty + 8*i];
}

// ---------------- bf16 split-3 GEMM via mma.sync ----------------------------
// D[M,N] = A[M,K] @ W  with BT = W^T stored [N,K].
// EPI: 0 = bias; 1 = bias + residual; 2 = bias + exact GELU
#define PITCH   40                       // bf16 elems per smem row (conflict-free ldmatrix)
#define TILE_B  (128 * PITCH * 2)        // 10240 B per tile
#define STAGE_B (4 * TILE_B)             // A_hi A_lo B_hi B_lo
#define GEMM_SMEM (2 * STAGE_B)          // 81920 B

template <int EPI>
__global__ __launch_bounds__(256) void mma_gemm_kernel(
    const float* __restrict__ A, const float* __restrict__ BT,
    const float* __restrict__ bias, const float* __restrict__ res,
    float* __restrict__ Cc, int M, int Nn, int K)
{
    extern __shared__ char sm[];
    const uint32_t sbase = smem_u32(sm);

    const int t    = threadIdx.x;
    const int lane = t & 31;
    const int warp = t >> 5;
    const int wm   = (warp & 3) * 32;      // warp m offset (4 warps down)
    const int wn   = (warp >> 2) * 64;     // warp n offset (2 warps across)
    const int bm   = blockIdx.y * 128;
    const int bn   = blockIdx.x * 128;

    // ldmatrix per-lane byte offsets (within a tile)
    const uint32_t aoffA =
        ((wm + (lane & 15)) * PITCH + ((lane >> 4) * 8)) * 2;
    const uint32_t aoffB =
        ((wn + (lane & 7) + ((lane >> 4) << 3)) * PITCH + (((lane >> 3) & 1) * 8)) * 2;

    float acc[2][8][4];
    #pragma unroll
    for (int mi = 0; mi < 2; mi++)
        #pragma unroll
        for (int j = 0; j < 8; j++)
            #pragma unroll
            for (int q = 0; q < 4; q++) acc[mi][j][q] = 0.0f;

    const int KT = K / 32;
    float4 pa[4], pb[4];

    // prologue: load tile 0 into regs
    #pragma unroll
    for (int i = 0; i < 4; i++) {
        const int idx = i * 256 + t;
        const int r = idx >> 3, kq = idx & 7;
        pa[i] = *reinterpret_cast<const float4*>(&A [(size_t)(bm + r) * K + kq * 4]);
        pb[i] = *reinterpret_cast<const float4*>(&BT[(size_t)(bn + r) * K + kq * 4]);
    }
    // STS tile 0 -> stage 0
    {
        char* s0 = sm;
        #pragma unroll
        for (int i = 0; i < 4; i++) {
            const int idx = i * 256 + t;
            const int r = idx >> 3, kq = idx & 7;
            const uint32_t off = (uint32_t)(r * PITCH + kq * 4) * 2;
            float4 a = pa[i];
            __nv_bfloat16 h0 = __float2bfloat16(a.x), h1 = __float2bfloat16(a.y),
                          h2 = __float2bfloat16(a.z), h3 = __float2bfloat16(a.w);
            uint2 H = { pck(h0, h1), pck(h2, h3) };
            uint2 L = { pck(__float2bfloat16(a.x - __bfloat162float(h0)),
                            __float2bfloat16(a.y - __bfloat162float(h1))),
                        pck(__float2bfloat16(a.z - __bfloat162float(h2)),
                            __float2bfloat16(a.w - __bfloat162float(h3))) };
            *reinterpret_cast<uint2*>(s0 + off)          = H;
            *reinterpret_cast<uint2*>(s0 + TILE_B + off) = L;
            float4 b = pb[i];
            __nv_bfloat16 g0 = __float2bfloat16(b.x), g1 = __float2bfloat16(b.y),
                          g2 = __float2bfloat16(b.z), g3 = __float2bfloat16(b.w);
            uint2 BH = { pck(g0, g1), pck(g2, g3) };
            uint2 BL = { pck(__float2bfloat16(b.x - __bfloat162float(g0)),
                             __float2bfloat16(b.y - __bfloat162float(g1))),
                         pck(__float2bfloat16(b.z - __bfloat162float(g2)),
                             __float2bfloat16(b.w - __bfloat162float(g3))) };
            *reinterpret_cast<uint2*>(s0 + 2 * TILE_B + off) = BH;
            *reinterpret_cast<uint2*>(s0 + 3 * TILE_B + off) = BL;
        }
    }
    __syncthreads();

    for (int kt = 0; kt < KT; kt++) {
        // prefetch next tile to regs
        if (kt + 1 < KT) {
            #pragma unroll
            for (int i = 0; i < 4; i++) {
                const int idx = i * 256 + t;
                const int r = idx >> 3, kq = idx & 7;
                pa[i] = *reinterpret_cast<const float4*>(
                    &A [(size_t)(bm + r) * K + (kt + 1) * 32 + kq * 4]);
                pb[i] = *reinterpret_cast<const float4*>(
                    &BT[(size_t)(bn + r) * K + (kt + 1) * 32 + kq * 4]);
            }
        }

        // compute current stage
        const uint32_t sA_hi = sbase + (uint32_t)(kt & 1) * STAGE_B;
        const uint32_t sA_lo = sA_hi + TILE_B;
        const uint32_t sB_hi = sA_hi + 2 * TILE_B;
        const uint32_t sB_lo = sA_hi + 3 * TILE_B;

        #pragma unroll
        for (int ks = 0; ks < 2; ks++) {
            uint32_t ah[2][4], al[2][4];
            ldmat4(ah[0], sA_hi + aoffA + ks * 32);
            ldmat4(ah[1], sA_hi + aoffA + 16 * PITCH * 2 + ks * 32);
            ldmat4(al[0], sA_lo + aoffA + ks * 32);
            ldmat4(al[1], sA_lo + aoffA + 16 * PITCH * 2 + ks * 32);

            uint32_t bh[8][2], bl[8][2];
            #pragma unroll
            for (int p = 0; p < 4; p++) {
                uint32_t r4[4];
                ldmat4(r4, sB_hi + aoffB + p * 16 * PITCH * 2 + ks * 32);
                bh[2*p][0] = r4[0]; bh[2*p][1] = r4[1];
                bh[2*p+1][0] = r4[2]; bh[2*p+1][1] = r4[3];
                ldmat4(r4, sB_lo + aoffB + p * 16 * PITCH * 2 + ks * 32);
                bl[2*p][0] = r4[0]; bl[2*p][1] = r4[1];
                bl[2*p+1][0] = r4[2]; bl[2*p+1][1] = r4[3];
            }
            #pragma unroll
            for (int mi = 0; mi < 2; mi++)
                #pragma unroll
                for (int j = 0; j < 8; j++) {
                    mma16816(acc[mi][j], ah[mi], bh[j][0], bh[j][1]);
                    mma16816(acc[mi][j], ah[mi], bl[j][0], bl[j][1]);
                    mma16816(acc[mi][j], al[mi], bh[j][0], bh[j][1]);
                }
        }
        __syncthreads();

        // STS next tile into other stage
        if (kt + 1 < KT) {
            char* s0 = sm + ((kt + 1) & 1) * STAGE_B;
            #pragma unroll
            for (int i = 0; i < 4; i++) {
                const int idx = i * 256 + t;
                const int r = idx >> 3, kq = idx & 7;
                const uint32_t off = (uint32_t)(r * PITCH + kq * 4) * 2;
                float4 a = pa[i];
                __nv_bfloat16 h0 = __float2bfloat16(a.x), h1 = __float2bfloat16(a.y),
                              h2 = __float2bfloat16(a.z), h3 = __float2bfloat16(a.w);
                uint2 H = { pck(h0, h1), pck(h2, h3) };
                uint2 L = { pck(__float2bfloat16(a.x - __bfloat162float(h0)),
                                __float2bfloat16(a.y - __bfloat162float(h1))),
                            pck(__float2bfloat16(a.z - __bfloat162float(h2)),
                                __float2bfloat16(a.w - __bfloat162float(h3))) };
                *reinterpret_cast<uint2*>(s0 + off)          = H;
                *reinterpret_cast<uint2*>(s0 + TILE_B + off) = L;
                float4 b = pb[i];
                __nv_bfloat16 g0 = __float2bfloat16(b.x), g1 = __float2bfloat16(b.y),
                              g2 = __float2bfloat16(b.z), g3 = __float2bfloat16(b.w);
                uint2 BH = { pck(g0, g1), pck(g2, g3) };
                uint2 BL = { pck(__float2bfloat16(b.x - __bfloat162float(g0)),
                                 __float2bfloat16(b.y - __bfloat162float(g1))),
                             pck(__float2bfloat16(b.z - __bfloat162float(g2)),
                                 __float2bfloat16(b.w - __bfloat162float(g3))) };
                *reinterpret_cast<uint2*>(s0 + 2 * TILE_B + off) = BH;
                *reinterpret_cast<uint2*>(s0 + 3 * TILE_B + off) = BL;
            }
            __syncthreads();
        }
    }

    // epilogue
    const int r0 = bm + wm + (lane >> 2);
    const int cb = bn + wn + (lane & 3) * 2;
    #pragma unroll
    for (int mi = 0; mi < 2; mi++) {
        #pragma unroll
        for (int j = 0; j < 8; j++) {
            const int col = cb + j * 8;
            const float b0v = bias[col], b1v = bias[col + 1];
            const int ra = r0 + mi * 16, rb = ra + 8;
            float2 v0 = { acc[mi][j][0] + b0v, acc[mi][j][1] + b1v };
            float2 v1 = { acc[mi][j][2] + b0v, acc[mi][j][3] + b1v };
            if (EPI == 1) {
                const float2 ra2 = *reinterpret_cast<const float2*>(
                    res + (size_t)ra * Nn + col);
                const float2 rb2 = *reinterpret_cast<const float2*>(
                    res + (size_t)rb * Nn + col);
                v0.x += ra2.x; v0.y += ra2.y; v1.x += rb2.x; v1.y += rb2.y;
            } else if (EPI == 2) {
                v0.x = gelu_exact(v0.x); v0.y = gelu_exact(v0.y);
                v1.x = gelu_exact(v1.x); v1.y = gelu_exact(v1.y);
            }
            *reinterpret_cast<float2*>(Cc + (size_t)ra * Nn + col) = v0;
            *reinterpret_cast<float2*>(Cc + (size_t)rb * Nn + col) = v1;
        }
    }
}

// ---------------- Flash attention (unchanged) -------------------------------
__global__ __launch_bounds__(128) void flash_attn_kernel(
    const float* __restrict__ q, const float* __restrict__ k,
    const float* __restrict__ v, float* __restrict__ o)
{
    constexpr int BKV = 32;
    __shared__ float Ks[BKV][HDIM];
    __shared__ float Vs[BKV][HDIM];
    __shared__ float Ss[128][BKV + 1];

    const int t = threadIdx.x;
    const int b = blockIdx.y >> 4;
    const int h = blockIdx.y & 15;
    const int n = blockIdx.x * 128 + t;

    const size_t rowbase = ((size_t)(b * NSEQ + n)) * CDIM + h * HDIM;
    const size_t kvbase  = ((size_t)b * NSEQ) * CDIM + h * HDIM;

    float qr[HDIM];
    #pragma unroll
    for (int i = 0; i < HDIM / 4; i++) {
        float4 q4 = *reinterpret_cast<const float4*>(q + rowbase + i * 4);
        qr[i*4+0] = q4.x; qr[i*4+1] = q4.y; qr[i*4+2] = q4.z; qr[i*4+3] = q4.w;
    }

    float m = -1e30f, l = 0.0f;
    float acc[HDIM];
    #pragma unroll
    for (int d = 0; d < HDIM; d++) acc[d] = 0.0f;

    for (int kv0 = 0; kv0 < NSEQ; kv0 += BKV) {
        #pragma unroll
        for (int i = 0; i < 4; i++) {
            const int idx = i * 128 + t;
            const int j   = idx >> 4;
            const int d4  = (idx & 15) * 4;
            const size_t g = kvbase + (size_t)(kv0 + j) * CDIM + d4;
            *reinterpret_cast<float4*>(&Ks[j][d4]) =
                *reinterpret_cast<const float4*>(k + g);
            *reinterpret_cast<float4*>(&Vs[j][d4]) =
                *reinterpret_cast<const float4*>(v + g);
        }
        __syncthreads();

        float smax = -1e30f;
        for (int j = 0; j < BKV; j++) {
            float s = 0.0f;
            #pragma unroll
            for (int d = 0; d < HDIM; d++) s = fmaf(qr[d], Ks[j][d], s);
            s *= 0.125f;
            Ss[t][j] = s;
            smax = fmaxf(smax, s);
        }
        const float mnew = fmaxf(m, smax);
        const float corr = __expf(m - mnew);
        l *= corr;
        #pragma unroll
        for (int d = 0; d < HDIM; d++) acc[d] *= corr;
        for (int j = 0; j < BKV; j++) {
            const float p = __expf(Ss[t][j] - mnew);
            l += p;
            #pragma unroll
            for (int d = 0; d < HDIM; d++) acc[d] = fmaf(p, Vs[j][d], acc[d]);
        }
        m = mnew;
        __syncthreads();
    }

    const float inv = 1.0f / l;
    #pragma unroll
    for (int i = 0; i < HDIM / 4; i++) {
        float4 o4;
        o4.x = acc[i*4+0] * inv; o4.y = acc[i*4+1] * inv;
        o4.z = acc[i*4+2] * inv; o4.w = acc[i*4+3] * inv;
        *reinterpret_cast<float4*>(o + rowbase + i * 4) = o4;
    }
}

// ---------------- host orchestration ----------------------------------------
extern "C" void kernel_launch(void* const* d_in, const int* in_sizes, int n_in,
                              void* d_out, int out_size)
{
    const float* x      = (const float*)d_in[0];
    const float* wq     = (const float*)d_in[1];
    const float* bq     = (const float*)d_in[2];
    const float* wk     = (const float*)d_in[3];
    const float* bk     = (const float*)d_in[4];
    const float* wv     = (const float*)d_in[5];
    const float* bv     = (const float*)d_in[6];
    const float* wo     = (const float*)d_in[7];
    const float* bo     = (const float*)d_in[8];
    const float* scale1 = (const float*)d_in[9];
    const float* scale2 = (const float*)d_in[10];
    const float* w1     = (const float*)d_in[11];
    const float* b1     = (const float*)d_in[12];
    const float* w2     = (const float*)d_in[13];
    const float* b2     = (const float*)d_in[14];
    float* out = (float*)d_out;

    float *p_xn, *p_q, *p_k, *p_v, *p_ctx, *p_x2, *p_xn2, *p_h;
    float *p_wqT, *p_wkT, *p_wvT, *p_woT, *p_w1T, *p_w2T;
    cudaGetSymbolAddress((void**)&p_xn,  g_xn);
    cudaGetSymbolAddress((void**)&p_q,   g_q);
    cudaGetSymbolAddress((void**)&p_k,   g_k);
    cudaGetSymbolAddress((void**)&p_v,   g_v);
    cudaGetSymbolAddress((void**)&p_ctx, g_ctx);
    cudaGetSymbolAddress((void**)&p_x2,  g_x2);
    cudaGetSymbolAddress((void**)&p_xn2, g_xn2);
    cudaGetSymbolAddress((void**)&p_h,   g_h);
    cudaGetSymbolAddress((void**)&p_wqT, g_wqT);
    cudaGetSymbolAddress((void**)&p_wkT, g_wkT);
    cudaGetSymbolAddress((void**)&p_wvT, g_wvT);
    cudaGetSymbolAddress((void**)&p_woT, g_woT);
    cudaGetSymbolAddress((void**)&p_w1T, g_w1T);
    cudaGetSymbolAddress((void**)&p_w2T, g_w2T);

    cudaFuncSetAttribute(mma_gemm_kernel<0>,
                         cudaFuncAttributeMaxDynamicSharedMemorySize, GEMM_SMEM);
    cudaFuncSetAttribute(mma_gemm_kernel<1>,
                         cudaFuncAttributeMaxDynamicSharedMemorySize, GEMM_SMEM);
    cudaFuncSetAttribute(mma_gemm_kernel<2>,
                         cudaFuncAttributeMaxDynamicSharedMemorySize, GEMM_SMEM);

    // weight transposes -> [N,K]
    {
        dim3 blk(32, 8);
        transpose_kernel<<<dim3(CDIM/32,  CDIM/32),  blk>>>(wq, p_wqT, CDIM, CDIM);
        transpose_kernel<<<dim3(CDIM/32,  CDIM/32),  blk>>>(wk, p_wkT, CDIM, CDIM);
        transpose_kernel<<<dim3(CDIM/32,  CDIM/32),  blk>>>(wv, p_wvT, CDIM, CDIM);
        transpose_kernel<<<dim3(CDIM/32,  CDIM/32),  blk>>>(wo, p_woT, CDIM, CDIM);
        transpose_kernel<<<dim3(FFDIM/32, CDIM/32),  blk>>>(w1, p_w1T, CDIM, FFDIM);
        transpose_kernel<<<dim3(CDIM/32,  FFDIM/32), blk>>>(w2, p_w2T, FFDIM, CDIM);
    }

    const dim3 g_cc(CDIM / 128,  MTOT / 128);   // (8, 32)
    const dim3 g_cf(FFDIM / 128, MTOT / 128);   // (32, 32)

    rmsnorm_kernel<<<MTOT, 256>>>(x, scale1, p_xn);

    mma_gemm_kernel<0><<<g_cc, 256, GEMM_SMEM>>>(p_xn, p_wqT, bq, nullptr, p_q,  MTOT, CDIM, CDIM);
    mma_gemm_kernel<0><<<g_cc, 256, GEMM_SMEM>>>(p_xn, p_wkT, bk, nullptr, p_k,  MTOT, CDIM, CDIM);
    mma_gemm_kernel<0><<<g_cc, 256, GEMM_SMEM>>>(p_xn, p_wvT, bv, nullptr, p_v,  MTOT, CDIM, CDIM);

    rotary_kernel<<<(MTOT * NHEAD) / 256, 256>>>(p_q);
    rotary_kernel<<<(MTOT * NHEAD) / 256, 256>>>(p_k);

    {
        dim3 grid(NSEQ / 128, 2 * NHEAD);
        flash_attn_kernel<<<grid, 128>>>(p_q, p_k, p_v, p_ctx);
    }

    mma_gemm_kernel<1><<<g_cc, 256, GEMM_SMEM>>>(p_ctx, p_woT, bo, x, p_x2, MTOT, CDIM, CDIM);

    rmsnorm_kernel<<<MTOT, 256>>>(p_x2, scale2, p_xn2);

    mma_gemm_kernel<2><<<g_cf, 256, GEMM_SMEM>>>(p_xn2, p_w1T, b1, nullptr, p_h, MTOT, FFDIM, CDIM);
    mma_gemm_kernel<1><<<g_cc, 256, GEMM_SMEM>>>(p_h,  p_w2T, b2, p_x2, out, MTOT, CDIM, FFDIM);
}

// round 4
// speedup vs baseline: 3.1392x; 1.9752x over previous
#include <cuda_runtime.h>
#include <cuda_bf16.h>
#include <math.h>
#include <stdint.h>

// Problem dims (fixed): B=2, N=2048, C=1024, H=16, D=64, FF=4096
#define MTOT 4096      // B*N
#define CDIM 1024
#define FFDIM 4096
#define NSEQ 2048
#define NHEAD 16
#define HDIM 64

// ---------------- scratch (no allocations allowed -> __device__ globals) ----
__device__ float g_xn [MTOT * CDIM];
__device__ float g_q  [MTOT * CDIM];
__device__ float g_k  [MTOT * CDIM];
__device__ float g_v  [MTOT * CDIM];
__device__ float g_ctx[MTOT * CDIM];
__device__ float g_x2 [MTOT * CDIM];
__device__ float g_xn2[MTOT * CDIM];
__device__ float g_h  [MTOT * FFDIM];
// transposed weights [N,K]
__device__ float g_wqT[CDIM * CDIM];
__device__ float g_wkT[CDIM * CDIM];
__device__ float g_wvT[CDIM * CDIM];
__device__ float g_woT[CDIM * CDIM];
__device__ float g_w1T[CDIM * FFDIM];
__device__ float g_w2T[CDIM * FFDIM];

// ---------------- small helpers --------------------------------------------
__device__ __forceinline__ uint32_t smem_u32(const void* p) {
    uint32_t a;
    asm("{ .reg .u64 t; cvta.to.shared.u64 t, %1; cvt.u32.u64 %0, t; }"
        : "=r"(a) : "l"(p));
    return a;
}
__device__ __forceinline__ void ldmat4(uint32_t (&r)[4], uint32_t addr) {
    asm volatile("ldmatrix.sync.aligned.m8n8.x4.shared.b16 {%0,%1,%2,%3}, [%4];"
                 : "=r"(r[0]), "=r"(r[1]), "=r"(r[2]), "=r"(r[3]) : "r"(addr));
}
__device__ __forceinline__ void ldmat4t(uint32_t (&r)[4], uint32_t addr) {
    asm volatile("ldmatrix.sync.aligned.m8n8.x4.trans.shared.b16 {%0,%1,%2,%3}, [%4];"
                 : "=r"(r[0]), "=r"(r[1]), "=r"(r[2]), "=r"(r[3]) : "r"(addr));
}
__device__ __forceinline__ void mma16816(float (&d)[4], const uint32_t (&a)[4],
                                         uint32_t b0, uint32_t b1) {
    asm volatile(
        "mma.sync.aligned.m16n8k16.row.col.f32.bf16.bf16.f32 "
        "{%0,%1,%2,%3}, {%4,%5,%6,%7}, {%8,%9}, {%0,%1,%2,%3};"
        : "+f"(d[0]), "+f"(d[1]), "+f"(d[2]), "+f"(d[3])
        : "r"(a[0]), "r"(a[1]), "r"(a[2]), "r"(a[3]), "r"(b0), "r"(b1));
}
__device__ __forceinline__ uint32_t pck(__nv_bfloat16 a, __nv_bfloat16 b) {
    __nv_bfloat162 t(a, b);
    return *reinterpret_cast<uint32_t*>(&t);
}
__device__ __forceinline__ uint32_t pckf(float a, float b) {
    return pck(__float2bfloat16(a), __float2bfloat16(b));
}
__device__ __forceinline__ float ex2f(float x) {
    float y;
    asm("ex2.approx.f32 %0, %1;" : "=f"(y) : "f"(x));
    return y;
}
__device__ __forceinline__ float gelu_exact(float x) {
    return 0.5f * x * (1.0f + erff(x * 0.7071067811865476f));
}

// ---------------- RMSNorm ---------------------------------------------------
__global__ __launch_bounds__(256) void rmsnorm_kernel(
    const float* __restrict__ x, const float* __restrict__ scale,
    float* __restrict__ out)
{
    __shared__ float red[8];
    const int row = blockIdx.x;
    const int t   = threadIdx.x;
    const float* xr = x + (size_t)row * CDIM;

    float4 v = *reinterpret_cast<const float4*>(xr + t * 4);
    float ss = v.x * v.x + v.y * v.y + v.z * v.z + v.w * v.w;
    #pragma unroll
    for (int o = 16; o > 0; o >>= 1) ss += __shfl_xor_sync(0xffffffffu, ss, o);
    if ((t & 31) == 0) red[t >> 5] = ss;
    __syncthreads();
    if (t < 8) {
        float s2 = red[t];
        #pragma unroll
        for (int o = 4; o > 0; o >>= 1) s2 += __shfl_xor_sync(0xffu, s2, o);
        if (t == 0) red[0] = s2;
    }
    __syncthreads();
    const float norm = sqrtf(red[0]);
    const float inv  = 1.0f / (norm * 0.03125f + 1e-8f);

    float4 sc = *reinterpret_cast<const float4*>(scale + t * 4);
    float4 o4;
    o4.x = v.x * sc.x * inv; o4.y = v.y * sc.y * inv;
    o4.z = v.z * sc.z * inv; o4.w = v.w * sc.w * inv;
    *reinterpret_cast<float4*>(out + (size_t)row * CDIM + t * 4) = o4;
}

// ---------------- rotary ----------------------------------------------------
__global__ __launch_bounds__(256) void rotary_kernel(float* __restrict__ p)
{
    const int idx = blockIdx.x * blockDim.x + threadIdx.x;
    float* r = p + (size_t)idx * HDIM;
    float v[HDIM];
    #pragma unroll
    for (int i = 0; i < HDIM / 4; i++) {
        float4 q4 = *reinterpret_cast<const float4*>(r + i * 4);
        v[i*4+0] = q4.x; v[i*4+1] = q4.y; v[i*4+2] = q4.z; v[i*4+3] = q4.w;
    }
    #pragma unroll
    for (int i = 0; i < HDIM / 4; i++) {
        float4 o4;
        o4.x = v[i*4+0] - v[(i*4+0 + HDIM-1) & (HDIM-1)];
        o4.y = v[i*4+1] - v[i*4+0];
        o4.z = v[i*4+2] - v[i*4+1];
        o4.w = v[i*4+3] - v[i*4+2];
        *reinterpret_cast<float4*>(r + i * 4) = o4;
    }
}

// ---------------- weight transpose: out[c][r] = in[r][c] --------------------
__global__ __launch_bounds__(256) void transpose_kernel(
    const float* __restrict__ in, float* __restrict__ out, int R, int Cc)
{
    __shared__ float ts[32][33];
    const int tx = threadIdx.x, ty = threadIdx.y;
    const int c0 = blockIdx.x * 32, r0 = blockIdx.y * 32;
    #pragma unroll
    for (int i = 0; i < 4; i++)
        ts[ty + 8*i][tx] = in[(size_t)(r0 + ty + 8*i) * Cc + c0 + tx];
    __syncthreads();
    #pragma unroll
    for (int i = 0; i < 4; i++)
        out[(size_t)(c0 + ty + 8*i) * R + r0 + tx] = ts[tx][ty + 8*i];
}

// ---------------- bf16 split-3 GEMM via mma.sync (unchanged from R3) --------
#define PITCH   40
#define TILE_B  (128 * PITCH * 2)
#define STAGE_B (4 * TILE_B)
#define GEMM_SMEM (2 * STAGE_B)

template <int EPI>
__global__ __launch_bounds__(256) void mma_gemm_kernel(
    const float* __restrict__ A, const float* __restrict__ BT,
    const float* __restrict__ bias, const float* __restrict__ res,
    float* __restrict__ Cc, int M, int Nn, int K)
{
    extern __shared__ char sm[];
    const uint32_t sbase = smem_u32(sm);

    const int t    = threadIdx.x;
    const int lane = t & 31;
    const int warp = t >> 5;
    const int wm   = (warp & 3) * 32;
    const int wn   = (warp >> 2) * 64;
    const int bm   = blockIdx.y * 128;
    const int bn   = blockIdx.x * 128;

    const uint32_t aoffA =
        ((wm + (lane & 15)) * PITCH + ((lane >> 4) * 8)) * 2;
    const uint32_t aoffB =
        ((wn + (lane & 7) + ((lane >> 4) << 3)) * PITCH + (((lane >> 3) & 1) * 8)) * 2;

    float acc[2][8][4];
    #pragma unroll
    for (int mi = 0; mi < 2; mi++)
        #pragma unroll
        for (int j = 0; j < 8; j++)
            #pragma unroll
            for (int q = 0; q < 4; q++) acc[mi][j][q] = 0.0f;

    const int KT = K / 32;
    float4 pa[4], pb[4];

    #pragma unroll
    for (int i = 0; i < 4; i++) {
        const int idx = i * 256 + t;
        const int r = idx >> 3, kq = idx & 7;
        pa[i] = *reinterpret_cast<const float4*>(&A [(size_t)(bm + r) * K + kq * 4]);
        pb[i] = *reinterpret_cast<const float4*>(&BT[(size_t)(bn + r) * K + kq * 4]);
    }
    {
        char* s0 = sm;
        #pragma unroll
        for (int i = 0; i < 4; i++) {
            const int idx = i * 256 + t;
            const int r = idx >> 3, kq = idx & 7;
            const uint32_t off = (uint32_t)(r * PITCH + kq * 4) * 2;
            float4 a = pa[i];
            __nv_bfloat16 h0 = __float2bfloat16(a.x), h1 = __float2bfloat16(a.y),
                          h2 = __float2bfloat16(a.z), h3 = __float2bfloat16(a.w);
            uint2 H = { pck(h0, h1), pck(h2, h3) };
            uint2 L = { pck(__float2bfloat16(a.x - __bfloat162float(h0)),
                            __float2bfloat16(a.y - __bfloat162float(h1))),
                        pck(__float2bfloat16(a.z - __bfloat162float(h2)),
                            __float2bfloat16(a.w - __bfloat162float(h3))) };
            *reinterpret_cast<uint2*>(s0 + off)          = H;
            *reinterpret_cast<uint2*>(s0 + TILE_B + off) = L;
            float4 b = pb[i];
            __nv_bfloat16 g0 = __float2bfloat16(b.x), g1 = __float2bfloat16(b.y),
                          g2 = __float2bfloat16(b.z), g3 = __float2bfloat16(b.w);
            uint2 BH = { pck(g0, g1), pck(g2, g3) };
            uint2 BL = { pck(__float2bfloat16(b.x - __bfloat162float(g0)),
                             __float2bfloat16(b.y - __bfloat162float(g1))),
                         pck(__float2bfloat16(b.z - __bfloat162float(g2)),
                             __float2bfloat16(b.w - __bfloat162float(g3))) };
            *reinterpret_cast<uint2*>(s0 + 2 * TILE_B + off) = BH;
            *reinterpret_cast<uint2*>(s0 + 3 * TILE_B + off) = BL;
        }
    }
    __syncthreads();

    for (int kt = 0; kt < KT; kt++) {
        if (kt + 1 < KT) {
            #pragma unroll
            for (int i = 0; i < 4; i++) {
                const int idx = i * 256 + t;
                const int r = idx >> 3, kq = idx & 7;
                pa[i] = *reinterpret_cast<const float4*>(
                    &A [(size_t)(bm + r) * K + (kt + 1) * 32 + kq * 4]);
                pb[i] = *reinterpret_cast<const float4*>(
                    &BT[(size_t)(bn + r) * K + (kt + 1) * 32 + kq * 4]);
            }
        }

        const uint32_t sA_hi = sbase + (uint32_t)(kt & 1) * STAGE_B;
        const uint32_t sA_lo = sA_hi + TILE_B;
        const uint32_t sB_hi = sA_hi + 2 * TILE_B;
        const uint32_t sB_lo = sA_hi + 3 * TILE_B;

        #pragma unroll
        for (int ks = 0; ks < 2; ks++) {
            uint32_t ah[2][4], al[2][4];
            ldmat4(ah[0], sA_hi + aoffA + ks * 32);
            ldmat4(ah[1], sA_hi + aoffA + 16 * PITCH * 2 + ks * 32);
            ldmat4(al[0], sA_lo + aoffA + ks * 32);
            ldmat4(al[1], sA_lo + aoffA + 16 * PITCH * 2 + ks * 32);

            uint32_t bh[8][2], bl[8][2];
            #pragma unroll
            for (int p = 0; p < 4; p++) {
                uint32_t r4[4];
                ldmat4(r4, sB_hi + aoffB + p * 16 * PITCH * 2 + ks * 32);
                bh[2*p][0] = r4[0]; bh[2*p][1] = r4[1];
                bh[2*p+1][0] = r4[2]; bh[2*p+1][1] = r4[3];
                ldmat4(r4, sB_lo + aoffB + p * 16 * PITCH * 2 + ks * 32);
                bl[2*p][0] = r4[0]; bl[2*p][1] = r4[1];
                bl[2*p+1][0] = r4[2]; bl[2*p+1][1] = r4[3];
            }
            #pragma unroll
            for (int mi = 0; mi < 2; mi++)
                #pragma unroll
                for (int j = 0; j < 8; j++) {
                    mma16816(acc[mi][j], ah[mi], bh[j][0], bh[j][1]);
                    mma16816(acc[mi][j], ah[mi], bl[j][0], bl[j][1]);
                    mma16816(acc[mi][j], al[mi], bh[j][0], bh[j][1]);
                }
        }
        __syncthreads();

        if (kt + 1 < KT) {
            char* s0 = sm + ((kt + 1) & 1) * STAGE_B;
            #pragma unroll
            for (int i = 0; i < 4; i++) {
                const int idx = i * 256 + t;
                const int r = idx >> 3, kq = idx & 7;
                const uint32_t off = (uint32_t)(r * PITCH + kq * 4) * 2;
                float4 a = pa[i];
                __nv_bfloat16 h0 = __float2bfloat16(a.x), h1 = __float2bfloat16(a.y),
                              h2 = __float2bfloat16(a.z), h3 = __float2bfloat16(a.w);
                uint2 H = { pck(h0, h1), pck(h2, h3) };
                uint2 L = { pck(__float2bfloat16(a.x - __bfloat162float(h0)),
                                __float2bfloat16(a.y - __bfloat162float(h1))),
                            pck(__float2bfloat16(a.z - __bfloat162float(h2)),
                                __float2bfloat16(a.w - __bfloat162float(h3))) };
                *reinterpret_cast<uint2*>(s0 + off)          = H;
                *reinterpret_cast<uint2*>(s0 + TILE_B + off) = L;
                float4 b = pb[i];
                __nv_bfloat16 g0 = __float2bfloat16(b.x), g1 = __float2bfloat16(b.y),
                              g2 = __float2bfloat16(b.z), g3 = __float2bfloat16(b.w);
                uint2 BH = { pck(g0, g1), pck(g2, g3) };
                uint2 BL = { pck(__float2bfloat16(b.x - __bfloat162float(g0)),
                                 __float2bfloat16(b.y - __bfloat162float(g1))),
                             pck(__float2bfloat16(b.z - __bfloat162float(g2)),
                                 __float2bfloat16(b.w - __bfloat162float(g3))) };
                *reinterpret_cast<uint2*>(s0 + 2 * TILE_B + off) = BH;
                *reinterpret_cast<uint2*>(s0 + 3 * TILE_B + off) = BL;
            }
            __syncthreads();
        }
    }

    const int r0 = bm + wm + (lane >> 2);
    const int cb = bn + wn + (lane & 3) * 2;
    #pragma unroll
    for (int mi = 0; mi < 2; mi++) {
        #pragma unroll
        for (int j = 0; j < 8; j++) {
            const int col = cb + j * 8;
            const float b0v = bias[col], b1v = bias[col + 1];
            const int ra = r0 + mi * 16, rb = ra + 8;
            float2 v0 = { acc[mi][j][0] + b0v, acc[mi][j][1] + b1v };
            float2 v1 = { acc[mi][j][2] + b0v, acc[mi][j][3] + b1v };
            if (EPI == 1) {
                const float2 ra2 = *reinterpret_cast<const float2*>(
                    res + (size_t)ra * Nn + col);
                const float2 rb2 = *reinterpret_cast<const float2*>(
                    res + (size_t)rb * Nn + col);
                v0.x += ra2.x; v0.y += ra2.y; v1.x += rb2.x; v1.y += rb2.y;
            } else if (EPI == 2) {
                v0.x = gelu_exact(v0.x); v0.y = gelu_exact(v0.y);
                v1.x = gelu_exact(v1.x); v1.y = gelu_exact(v1.y);
            }
            *reinterpret_cast<float2*>(Cc + (size_t)ra * Nn + col) = v0;
            *reinterpret_cast<float2*>(Cc + (size_t)rb * Nn + col) = v1;
        }
    }
}

// ---------------- Tensor-core flash attention --------------------------------
// BM=128 (8 warps x 16 rows), BN=64 kv tile, D=64. bf16 mma.sync.
#define APITCH 72                          // bf16 elems per smem row
#define ATILE  (64 * APITCH * 2)           // 9216 B (one K or V tile)
#define ASMEM  (2 * 2 * ATILE)             // 36864 B

__global__ __launch_bounds__(256) void flash_attn_mma_kernel(
    const float* __restrict__ q, const float* __restrict__ k,
    const float* __restrict__ v, float* __restrict__ o)
{
    extern __shared__ char shm[];
    const uint32_t sbase = smem_u32(shm);

    const int t    = threadIdx.x;
    const int lane = t & 31;
    const int warp = t >> 5;
    const int bh   = blockIdx.y;
    const int b    = bh >> 4;
    const int h    = bh & 15;
    const int q0   = blockIdx.x * 128;     // first query row of CTA
    const int wm   = warp * 16;            // warp's 16 query rows

    const float cscale = 0.125f * 1.4426950408889634f;  // fold 1/sqrt(D)*log2e into Q

    // ---- phase 0: Q -> smem (bf16, scaled), then frags ----
    {
        const int r   = t >> 1;                // 0..127
        const int cb0 = (t & 1) * 8;           // float4 slot base
        #pragma unroll
        for (int i = 0; i < 8; i++) {
            const int c4 = cb0 + i;            // 0..15
            float4 f = *reinterpret_cast<const float4*>(
                q + ((size_t)(b * NSEQ + q0 + r) * CDIM + h * HDIM + c4 * 4));
            uint2 hq = { pckf(f.x * cscale, f.y * cscale),
                         pckf(f.z * cscale, f.w * cscale) };
            *reinterpret_cast<uint2*>(shm + (r * APITCH + c4 * 4) * 2) = hq;
        }
    }
    __syncthreads();
    uint32_t qf[4][4];
    #pragma unroll
    for (int ks = 0; ks < 4; ks++)
        ldmat4(qf[ks], sbase + ((wm + (lane & 15)) * APITCH + ks * 16 + (lane >> 4) * 8) * 2);
    __syncthreads();

    // ---- state ----
    float m0 = -1e30f, m1 = -1e30f, l0 = 0.0f, l1 = 0.0f;
    float oa[8][4];
    #pragma unroll
    for (int j = 0; j < 8; j++)
        #pragma unroll
        for (int p = 0; p < 4; p++) oa[j][p] = 0.0f;

    // K/V tile load lambda-ish (manual): r = t>>2 (0..63), c4 base = t&3
    const int lr  = t >> 2;
    const int lc  = t & 3;
    const size_t kvrow0 = (size_t)(b * NSEQ) * CDIM + h * HDIM;

    uint2 kr[4], vr[4];
    #define LOAD_KV(tile)                                                     \
        {                                                                     \
            const size_t gbase = kvrow0 + (size_t)((tile) * 64 + lr) * CDIM;  \
            _Pragma("unroll")                                                 \
            for (int i = 0; i < 4; i++) {                                     \
                const int c4 = lc + i * 4;                                    \
                float4 fk = *reinterpret_cast<const float4*>(k + gbase + c4 * 4); \
                float4 fv = *reinterpret_cast<const float4*>(v + gbase + c4 * 4); \
                kr[i].x = pckf(fk.x, fk.y); kr[i].y = pckf(fk.z, fk.w);       \
                vr[i].x = pckf(fv.x, fv.y); vr[i].y = pckf(fv.z, fv.w);       \
            }                                                                 \
        }
    #define STS_KV(stg)                                                       \
        {                                                                     \
            char* kb = shm + (stg) * 2 * ATILE;                               \
            char* vb = kb + ATILE;                                            \
            _Pragma("unroll")                                                 \
            for (int i = 0; i < 4; i++) {                                     \
                const int c4 = lc + i * 4;                                    \
                *reinterpret_cast<uint2*>(kb + (lr * APITCH + c4 * 4) * 2) = kr[i]; \
                *reinterpret_cast<uint2*>(vb + (lr * APITCH + c4 * 4) * 2) = vr[i]; \
            }                                                                 \
        }

    LOAD_KV(0);
    STS_KV(0);
    __syncthreads();

    const int NT = NSEQ / 64;   // 32
    for (int kt = 0; kt < NT; kt++) {
        if (kt + 1 < NT) LOAD_KV(kt + 1);

        const uint32_t kb = sbase + (uint32_t)(kt & 1) * 2 * ATILE;
        const uint32_t vb = kb + ATILE;

        // ---- S = Q @ K^T (in exp2 units) ----
        float sc[8][4];
        #pragma unroll
        for (int j = 0; j < 8; j++)
            #pragma unroll
            for (int p = 0; p < 4; p++) sc[j][p] = 0.0f;

        #pragma unroll
        for (int ks = 0; ks < 4; ks++) {
            #pragma unroll
            for (int p = 0; p < 4; p++) {
                uint32_t r4[4];
                ldmat4(r4, kb + ((p * 16 + (lane & 7) + ((lane >> 4) << 3)) * APITCH
                                 + ks * 16 + ((lane >> 3) & 1) * 8) * 2);
                mma16816(sc[2*p],   qf[ks], r4[0], r4[1]);
                mma16816(sc[2*p+1], qf[ks], r4[2], r4[3]);
            }
        }

        // ---- online softmax ----
        float mx0 = sc[0][0], mx1 = sc[0][2];
        #pragma unroll
        for (int j = 0; j < 8; j++) {
            mx0 = fmaxf(mx0, fmaxf(sc[j][0], sc[j][1]));
            mx1 = fmaxf(mx1, fmaxf(sc[j][2], sc[j][3]));
        }
        mx0 = fmaxf(mx0, __shfl_xor_sync(0xffffffffu, mx0, 1));
        mx0 = fmaxf(mx0, __shfl_xor_sync(0xffffffffu, mx0, 2));
        mx1 = fmaxf(mx1, __shfl_xor_sync(0xffffffffu, mx1, 1));
        mx1 = fmaxf(mx1, __shfl_xor_sync(0xffffffffu, mx1, 2));

        const float mn0 = fmaxf(m0, mx0), mn1 = fmaxf(m1, mx1);
        const float cr0 = ex2f(m0 - mn0), cr1 = ex2f(m1 - mn1);
        m0 = mn0; m1 = mn1;

        float rs0 = 0.0f, rs1 = 0.0f;
        uint32_t pf[4][4];
        #pragma unroll
        for (int j = 0; j < 8; j++) {
            const float p0 = ex2f(sc[j][0] - mn0);
            const float p1 = ex2f(sc[j][1] - mn0);
            const float p2 = ex2f(sc[j][2] - mn1);
            const float p3 = ex2f(sc[j][3] - mn1);
            rs0 += p0 + p1; rs1 += p2 + p3;
            pf[j >> 1][(j & 1) * 2 + 0] = pckf(p0, p1);
            pf[j >> 1][(j & 1) * 2 + 1] = pckf(p2, p3);
        }
        // pf[j2] = {a0 (r,k2c) from tile 2j2, a1 (r+8), a2 (r,k+8) from 2j2+1, a3}
        // our fill order put a1 at index1 only when j even/odd handled:
        // index mapping above: j even -> slots 0,1 ; j odd -> slots 2,3. Correct:
        // slots {0,1} = tile 2j2 (c0c1, c2c3) ; {2,3} = tile 2j2+1. Matches A frag.

        rs0 += __shfl_xor_sync(0xffffffffu, rs0, 1);
        rs0 += __shfl_xor_sync(0xffffffffu, rs0, 2);
        rs1 += __shfl_xor_sync(0xffffffffu, rs1, 1);
        rs1 += __shfl_xor_sync(0xffffffffu, rs1, 2);
        l0 = l0 * cr0 + rs0;
        l1 = l1 * cr1 + rs1;

        #pragma unroll
        for (int j = 0; j < 8; j++) {
            oa[j][0] *= cr0; oa[j][1] *= cr0;
            oa[j][2] *= cr1; oa[j][3] *= cr1;
        }

        // ---- O += P @ V ----
        #pragma unroll
        for (int ks = 0; ks < 4; ks++) {
            #pragma unroll
            for (int p = 0; p < 4; p++) {
                uint32_t r4[4];
                ldmat4t(r4, vb + ((ks * 16 + (lane & 15)) * APITCH
                                  + p * 16 + ((lane >> 4) << 3)) * 2);
                mma16816(oa[2*p],   pf[ks], r4[0], r4[1]);
                mma16816(oa[2*p+1], pf[ks], r4[2], r4[3]);
            }
        }

        __syncthreads();
        if (kt + 1 < NT) {
            STS_KV((kt + 1) & 1);
            __syncthreads();
        }
    }

    // ---- epilogue ----
    const float iv0 = 1.0f / l0, iv1 = 1.0f / l1;
    const int ra = q0 + wm + (lane >> 2);
    const int rb = ra + 8;
    #pragma unroll
    for (int j = 0; j < 8; j++) {
        const int col = h * HDIM + j * 8 + (lane & 3) * 2;
        float2 w0 = { oa[j][0] * iv0, oa[j][1] * iv0 };
        float2 w1 = { oa[j][2] * iv1, oa[j][3] * iv1 };
        *reinterpret_cast<float2*>(o + (size_t)(b * NSEQ + ra) * CDIM + col) = w0;
        *reinterpret_cast<float2*>(o + (size_t)(b * NSEQ + rb) * CDIM + col) = w1;
    }
}

// ---------------- host orchestration ----------------------------------------
extern "C" void kernel_launch(void* const* d_in, const int* in_sizes, int n_in,
                              void* d_out, int out_size)
{
    const float* x      = (const float*)d_in[0];
    const float* wq     = (const float*)d_in[1];
    const float* bq     = (const float*)d_in[2];
    const float* wk     = (const float*)d_in[3];
    const float* bk     = (const float*)d_in[4];
    const float* wv     = (const float*)d_in[5];
    const float* bv     = (const float*)d_in[6];
    const float* wo     = (const float*)d_in[7];
    const float* bo     = (const float*)d_in[8];
    const float* scale1 = (const float*)d_in[9];
    const float* scale2 = (const float*)d_in[10];
    const float* w1     = (const float*)d_in[11];
    const float* b1     = (const float*)d_in[12];
    const float* w2     = (const float*)d_in[13];
    const float* b2     = (const float*)d_in[14];
    float* out = (float*)d_out;

    float *p_xn, *p_q, *p_k, *p_v, *p_ctx, *p_x2, *p_xn2, *p_h;
    float *p_wqT, *p_wkT, *p_wvT, *p_woT, *p_w1T, *p_w2T;
    cudaGetSymbolAddress((void**)&p_xn,  g_xn);
    cudaGetSymbolAddress((void**)&p_q,   g_q);
    cudaGetSymbolAddress((void**)&p_k,   g_k);
    cudaGetSymbolAddress((void**)&p_v,   g_v);
    cudaGetSymbolAddress((void**)&p_ctx, g_ctx);
    cudaGetSymbolAddress((void**)&p_x2,  g_x2);
    cudaGetSymbolAddress((void**)&p_xn2, g_xn2);
    cudaGetSymbolAddress((void**)&p_h,   g_h);
    cudaGetSymbolAddress((void**)&p_wqT, g_wqT);
    cudaGetSymbolAddress((void**)&p_wkT, g_wkT);
    cudaGetSymbolAddress((void**)&p_wvT, g_wvT);
    cudaGetSymbolAddress((void**)&p_woT, g_woT);
    cudaGetSymbolAddress((void**)&p_w1T, g_w1T);
    cudaGetSymbolAddress((void**)&p_w2T, g_w2T);

    cudaFuncSetAttribute(mma_gemm_kernel<0>,
                         cudaFuncAttributeMaxDynamicSharedMemorySize, GEMM_SMEM);
    cudaFuncSetAttribute(mma_gemm_kernel<1>,
                         cudaFuncAttributeMaxDynamicSharedMemorySize, GEMM_SMEM);
    cudaFuncSetAttribute(mma_gemm_kernel<2>,
                         cudaFuncAttributeMaxDynamicSharedMemorySize, GEMM_SMEM);
    cudaFuncSetAttribute(flash_attn_mma_kernel,
                         cudaFuncAttributeMaxDynamicSharedMemorySize, ASMEM);

    {
        dim3 blk(32, 8);
        transpose_kernel<<<dim3(CDIM/32,  CDIM/32),  blk>>>(wq, p_wqT, CDIM, CDIM);
        transpose_kernel<<<dim3(CDIM/32,  CDIM/32),  blk>>>(wk, p_wkT, CDIM, CDIM);
        transpose_kernel<<<dim3(CDIM/32,  CDIM/32),  blk>>>(wv, p_wvT, CDIM, CDIM);
        transpose_kernel<<<dim3(CDIM/32,  CDIM/32),  blk>>>(wo, p_woT, CDIM, CDIM);
        transpose_kernel<<<dim3(FFDIM/32, CDIM/32),  blk>>>(w1, p_w1T, CDIM, FFDIM);
        transpose_kernel<<<dim3(CDIM/32,  FFDIM/32), blk>>>(w2, p_w2T, FFDIM, CDIM);
    }

    const dim3 g_cc(CDIM / 128,  MTOT / 128);
    const dim3 g_cf(FFDIM / 128, MTOT / 128);

    rmsnorm_kernel<<<MTOT, 256>>>(x, scale1, p_xn);

    mma_gemm_kernel<0><<<g_cc, 256, GEMM_SMEM>>>(p_xn, p_wqT, bq, nullptr, p_q,  MTOT, CDIM, CDIM);
    mma_gemm_kernel<0><<<g_cc, 256, GEMM_SMEM>>>(p_xn, p_wkT, bk, nullptr, p_k,  MTOT, CDIM, CDIM);
    mma_gemm_kernel<0><<<g_cc, 256, GEMM_SMEM>>>(p_xn, p_wvT, bv, nullptr, p_v,  MTOT, CDIM, CDIM);

    rotary_kernel<<<(MTOT * NHEAD) / 256, 256>>>(p_q);
    rotary_kernel<<<(MTOT * NHEAD) / 256, 256>>>(p_k);

    {
        dim3 grid(NSEQ / 128, 2 * NHEAD);
        flash_attn_mma_kernel<<<grid, 256, ASMEM>>>(p_q, p_k, p_v, p_ctx);
    }

    mma_gemm_kernel<1><<<g_cc, 256, GEMM_SMEM>>>(p_ctx, p_woT, bo, x, p_x2, MTOT, CDIM, CDIM);

    rmsnorm_kernel<<<MTOT, 256>>>(p_x2, scale2, p_xn2);

    mma_gemm_kernel<2><<<g_cf, 256, GEMM_SMEM>>>(p_xn2, p_w1T, b1, nullptr, p_h, MTOT, FFDIM, CDIM);
    mma_gemm_kernel<1><<<g_cc, 256, GEMM_SMEM>>>(p_h,  p_w2T, b2, p_x2, out, MTOT, CDIM, FFDIM);
}

// round 5
// speedup vs baseline: 3.8428x; 1.2242x over previous
#include <cuda_runtime.h>
#include <cuda_bf16.h>
#include <math.h>
#include <stdint.h>

// Problem dims (fixed): B=2, N=2048, C=1024, H=16, D=64, FF=4096
#define MTOT 4096
#define CDIM 1024
#define FFDIM 4096
#define NSEQ 2048
#define NHEAD 16
#define HDIM 64
#define QKVN 3072

// ---------------- scratch (no allocations -> __device__ globals) ------------
__device__ __nv_bfloat16 g_xnh [MTOT*CDIM], g_xnl [MTOT*CDIM];
__device__ float         g_qkv [MTOT*QKVN];
__device__ __nv_bfloat16 g_qb  [MTOT*CDIM], g_kb  [MTOT*CDIM], g_vb[MTOT*CDIM];
__device__ __nv_bfloat16 g_ctxh[MTOT*CDIM], g_ctxl[MTOT*CDIM];
__device__ float         g_x2  [MTOT*CDIM];
__device__ __nv_bfloat16 g_xn2h[MTOT*CDIM], g_xn2l[MTOT*CDIM];
__device__ __nv_bfloat16 g_hh  [MTOT*FFDIM], g_hl [MTOT*FFDIM];
__device__ __nv_bfloat16 g_wqkvh[QKVN*CDIM], g_wqkvl[QKVN*CDIM];
__device__ __nv_bfloat16 g_woh [CDIM*CDIM],  g_wol [CDIM*CDIM];
__device__ __nv_bfloat16 g_w1h [FFDIM*CDIM], g_w1l [FFDIM*CDIM];
__device__ __nv_bfloat16 g_w2h [CDIM*FFDIM], g_w2l [CDIM*FFDIM];
__device__ float         g_bqkv[QKVN];

// ---------------- helpers ----------------------------------------------------
__device__ __forceinline__ uint32_t smem_u32(const void* p) {
    uint32_t a;
    asm("{ .reg .u64 t; cvta.to.shared.u64 t, %1; cvt.u32.u64 %0, t; }"
        : "=r"(a) : "l"(p));
    return a;
}
__device__ __forceinline__ void ldmat4(uint32_t (&r)[4], uint32_t addr) {
    asm volatile("ldmatrix.sync.aligned.m8n8.x4.shared.b16 {%0,%1,%2,%3}, [%4];"
                 : "=r"(r[0]), "=r"(r[1]), "=r"(r[2]), "=r"(r[3]) : "r"(addr));
}
__device__ __forceinline__ void ldmat4t(uint32_t (&r)[4], uint32_t addr) {
    asm volatile("ldmatrix.sync.aligned.m8n8.x4.trans.shared.b16 {%0,%1,%2,%3}, [%4];"
                 : "=r"(r[0]), "=r"(r[1]), "=r"(r[2]), "=r"(r[3]) : "r"(addr));
}
__device__ __forceinline__ void mma16816(float (&d)[4], const uint32_t (&a)[4],
                                         uint32_t b0, uint32_t b1) {
    asm volatile(
        "mma.sync.aligned.m16n8k16.row.col.f32.bf16.bf16.f32 "
        "{%0,%1,%2,%3}, {%4,%5,%6,%7}, {%8,%9}, {%0,%1,%2,%3};"
        : "+f"(d[0]), "+f"(d[1]), "+f"(d[2]), "+f"(d[3])
        : "r"(a[0]), "r"(a[1]), "r"(a[2]), "r"(a[3]), "r"(b0), "r"(b1));
}
__device__ __forceinline__ uint32_t pck(__nv_bfloat16 a, __nv_bfloat16 b) {
    __nv_bfloat162 t(a, b);
    return *reinterpret_cast<uint32_t*>(&t);
}
__device__ __forceinline__ void splitbf(float x, __nv_bfloat16& h, __nv_bfloat16& l) {
    h = __float2bfloat16(x);
    l = __float2bfloat16(x - __bfloat162float(h));
}
__device__ __forceinline__ float ex2f(float x) {
    float y;
    asm("ex2.approx.f32 %0, %1;" : "=f"(y) : "f"(x));
    return y;
}
__device__ __forceinline__ float gelu_exact(float x) {
    return 0.5f * x * (1.0f + erff(x * 0.7071067811865476f));
}
__device__ __forceinline__ void cp16(uint32_t d, const void* s) {
    asm volatile("cp.async.cg.shared.global [%0], [%1], 16;" :: "r"(d), "l"(s));
}
__device__ __forceinline__ void cpcommit() {
    asm volatile("cp.async.commit_group;" ::: "memory");
}
__device__ __forceinline__ void cpwait0() {
    asm volatile("cp.async.wait_group 0;" ::: "memory");
}
__device__ __forceinline__ void cpwait1() {
    asm volatile("cp.async.wait_group 1;" ::: "memory");
}

// ---------------- misc small kernels ----------------------------------------
__global__ void bias_concat_kernel(const float* bq, const float* bk,
                                   const float* bv, float* out)
{
    const int i = blockIdx.x * 256 + threadIdx.x;
    float v;
    if (i < 1024)      v = bq[i];
    else if (i < 2048) v = bk[i - 1024];
    else               v = bv[i - 2048];
    out[i] = v;
}

// w [R,Cc] fp32 -> wT hi/lo [Cc,R] bf16
__global__ __launch_bounds__(256) void transpose_split_kernel(
    const float* __restrict__ in, __nv_bfloat16* __restrict__ oh,
    __nv_bfloat16* __restrict__ ol, int R, int Cc)
{
    __shared__ float ts[32][33];
    const int tx = threadIdx.x, ty = threadIdx.y;
    const int c0 = blockIdx.x * 32, r0 = blockIdx.y * 32;
    #pragma unroll
    for (int i = 0; i < 4; i++)
        ts[ty + 8*i][tx] = in[(size_t)(r0 + ty + 8*i) * Cc + c0 + tx];
    __syncthreads();
    #pragma unroll
    for (int i = 0; i < 4; i++) {
        const float v = ts[tx][ty + 8*i];
        __nv_bfloat16 h, l;
        splitbf(v, h, l);
        const size_t o = (size_t)(c0 + ty + 8*i) * R + r0 + tx;
        oh[o] = h; ol[o] = l;
    }
}

// RMSNorm -> bf16 hi/lo
__global__ __launch_bounds__(256) void rmsnorm_split_kernel(
    const float* __restrict__ x, const float* __restrict__ scale,
    __nv_bfloat16* __restrict__ oh, __nv_bfloat16* __restrict__ ol)
{
    __shared__ float red[8];
    const int row = blockIdx.x;
    const int t   = threadIdx.x;
    const float* xr = x + (size_t)row * CDIM;

    float4 v = *reinterpret_cast<const float4*>(xr + t * 4);
    float ss = v.x * v.x + v.y * v.y + v.z * v.z + v.w * v.w;
    #pragma unroll
    for (int o = 16; o > 0; o >>= 1) ss += __shfl_xor_sync(0xffffffffu, ss, o);
    if ((t & 31) == 0) red[t >> 5] = ss;
    __syncthreads();
    if (t < 8) {
        float s2 = red[t];
        #pragma unroll
        for (int o = 4; o > 0; o >>= 1) s2 += __shfl_xor_sync(0xffu, s2, o);
        if (t == 0) red[0] = s2;
    }
    __syncthreads();
    const float norm = sqrtf(red[0]);
    const float inv  = 1.0f / (norm * 0.03125f + 1e-8f);

    float4 sc = *reinterpret_cast<const float4*>(scale + t * 4);
    float o0 = v.x * sc.x * inv, o1 = v.y * sc.y * inv;
    float o2 = v.z * sc.z * inv, o3 = v.w * sc.w * inv;
    __nv_bfloat16 h0, l0, h1, l1, h2, l2, h3, l3;
    splitbf(o0, h0, l0); splitbf(o1, h1, l1);
    splitbf(o2, h2, l2); splitbf(o3, h3, l3);
    uint2 H = { pck(h0, h1), pck(h2, h3) };
    uint2 L = { pck(l0, l1), pck(l2, l3) };
    *reinterpret_cast<uint2*>(oh + (size_t)row * CDIM + t * 4) = H;
    *reinterpret_cast<uint2*>(ol + (size_t)row * CDIM + t * 4) = L;
}

// post-QKV: rotary on q (then scale), rotary on k, convert v; fp32 -> bf16
// grid (MTOT*NHEAD/256, 3); sec 0=q,1=k,2=v
__global__ __launch_bounds__(256) void postqkv_kernel(
    const float* __restrict__ qkv, __nv_bfloat16* __restrict__ qb,
    __nv_bfloat16* __restrict__ kb, __nv_bfloat16* __restrict__ vb)
{
    const int id  = blockIdx.x * 256 + threadIdx.x;
    const int sec = blockIdx.y;
    const int m   = id >> 4;
    const int h   = id & 15;
    const float* src = qkv + (size_t)m * QKVN + sec * 1024 + h * HDIM;
    __nv_bfloat16* dst = (sec == 0 ? qb : sec == 1 ? kb : vb)
                         + (size_t)m * CDIM + h * HDIM;

    float v[HDIM];
    #pragma unroll
    for (int i = 0; i < HDIM / 4; i++) {
        float4 f = *reinterpret_cast<const float4*>(src + i * 4);
        v[i*4+0] = f.x; v[i*4+1] = f.y; v[i*4+2] = f.z; v[i*4+3] = f.w;
    }
    const float cscale = 0.125f * 1.4426950408889634f;
    float o[HDIM];
    if (sec == 2) {
        #pragma unroll
        for (int d = 0; d < HDIM; d++) o[d] = v[d];
    } else {
        #pragma unroll
        for (int d = 0; d < HDIM; d++)
            o[d] = v[d] - v[(d + HDIM - 1) & (HDIM - 1)];
        if (sec == 0) {
            #pragma unroll
            for (int d = 0; d < HDIM; d++) o[d] *= cscale;
        }
    }
    #pragma unroll
    for (int i = 0; i < HDIM / 8; i++) {
        uint4 w;
        w.x = pck(__float2bfloat16(o[i*8+0]), __float2bfloat16(o[i*8+1]));
        w.y = pck(__float2bfloat16(o[i*8+2]), __float2bfloat16(o[i*8+3]));
        w.z = pck(__float2bfloat16(o[i*8+4]), __float2bfloat16(o[i*8+5]));
        w.w = pck(__float2bfloat16(o[i*8+6]), __float2bfloat16(o[i*8+7]));
        *reinterpret_cast<uint4*>(dst + i * 8) = w;
    }
}

// ---------------- GEMM v2: pre-split bf16 operands, cp.async pipeline -------
// D[M,N] = (Ah+Al)[M,K] @ (Bh+Bl)^T[N,K], 3-term split accumulation.
// EPI: 0 bias -> fp32 Co ; 1 bias+res -> fp32 Co ; 2 bias+gelu -> split Ch/Cl
#define PITCH 40
#define TILEB (128 * PITCH * 2)     // 10240 B
#define STAGEB (4 * TILEB)          // 40960 B
#define GSMEM (2 * STAGEB)          // 81920 B

template <int EPI>
__global__ __launch_bounds__(256, 2) void gemm2_kernel(
    const __nv_bfloat16* __restrict__ Ah, const __nv_bfloat16* __restrict__ Al,
    const __nv_bfloat16* __restrict__ Bh, const __nv_bfloat16* __restrict__ Bl,
    const float* __restrict__ bias, const float* __restrict__ res,
    float* __restrict__ Co, __nv_bfloat16* __restrict__ Ch,
    __nv_bfloat16* __restrict__ Cl, int M, int Nn, int K)
{
    extern __shared__ char sm[];
    const uint32_t sbase = smem_u32(sm);

    const int t    = threadIdx.x;
    const int lane = t & 31;
    const int warp = t >> 5;
    const int wm   = (warp & 3) * 32;
    const int wn   = (warp >> 2) * 64;
    const int bm   = blockIdx.y * 128;
    const int bn   = blockIdx.x * 128;

    const uint32_t aoffA =
        ((wm + (lane & 15)) * PITCH + ((lane >> 4) * 8)) * 2;
    const uint32_t aoffB =
        ((wn + (lane & 7) + ((lane >> 4) << 3)) * PITCH + (((lane >> 3) & 1) * 8)) * 2;

    float acc[2][8][4];
    #pragma unroll
    for (int mi = 0; mi < 2; mi++)
        #pragma unroll
        for (int j = 0; j < 8; j++)
            #pragma unroll
            for (int q = 0; q < 4; q++) acc[mi][j][q] = 0.0f;

    const int KT = K / 32;

    #define G_ISSUE(kt, stg)                                                  \
        { const uint32_t sb = sbase + (uint32_t)(stg) * STAGEB;               \
          _Pragma("unroll")                                                   \
          for (int i = 0; i < 2; i++) {                                       \
              const int idx = i * 256 + t;                                    \
              const int row = idx >> 2, c = idx & 3;                          \
              const uint32_t d = sb + row * (PITCH * 2) + c * 16;             \
              const size_t ga = (size_t)(bm + row) * K + (kt) * 32 + c * 8;   \
              const size_t gb = (size_t)(bn + row) * K + (kt) * 32 + c * 8;   \
              cp16(d,             Ah + ga);                                   \
              cp16(d + TILEB,     Al + ga);                                   \
              cp16(d + 2 * TILEB, Bh + gb);                                   \
              cp16(d + 3 * TILEB, Bl + gb);                                   \
          } }

    G_ISSUE(0, 0); cpcommit();

    for (int kt = 0; kt < KT; kt++) {
        if (kt + 1 < KT) { G_ISSUE(kt + 1, (kt + 1) & 1); cpcommit(); cpwait1(); }
        else             { cpwait0(); }
        __syncthreads();

        const uint32_t sb  = sbase + (uint32_t)(kt & 1) * STAGEB;
        const uint32_t sAh = sb;
        const uint32_t sAl = sb + TILEB;
        const uint32_t sBh = sb + 2 * TILEB;
        const uint32_t sBl = sb + 3 * TILEB;

        #pragma unroll
        for (int ks = 0; ks < 2; ks++) {
            uint32_t ah[2][4], al[2][4];
            ldmat4(ah[0], sAh + aoffA + ks * 32);
            ldmat4(ah[1], sAh + aoffA + 16 * PITCH * 2 + ks * 32);
            ldmat4(al[0], sAl + aoffA + ks * 32);
            ldmat4(al[1], sAl + aoffA + 16 * PITCH * 2 + ks * 32);
            #pragma unroll
            for (int p = 0; p < 4; p++) {
                uint32_t bh4[4], bl4[4];
                ldmat4(bh4, sBh + aoffB + p * 16 * PITCH * 2 + ks * 32);
                ldmat4(bl4, sBl + aoffB + p * 16 * PITCH * 2 + ks * 32);
                #pragma unroll
                for (int mi = 0; mi < 2; mi++) {
                    mma16816(acc[mi][2*p],   ah[mi], bh4[0], bh4[1]);
                    mma16816(acc[mi][2*p+1], ah[mi], bh4[2], bh4[3]);
                    mma16816(acc[mi][2*p],   ah[mi], bl4[0], bl4[1]);
                    mma16816(acc[mi][2*p+1], ah[mi], bl4[2], bl4[3]);
                    mma16816(acc[mi][2*p],   al[mi], bh4[0], bh4[1]);
                    mma16816(acc[mi][2*p+1], al[mi], bh4[2], bh4[3]);
                }
            }
        }
        __syncthreads();
    }
    #undef G_ISSUE

    const int r0 = bm + wm + (lane >> 2);
    const int cb = bn + wn + (lane & 3) * 2;
    #pragma unroll
    for (int mi = 0; mi < 2; mi++) {
        #pragma unroll
        for (int j = 0; j < 8; j++) {
            const int col = cb + j * 8;
            const float b0v = bias[col], b1v = bias[col + 1];
            const int ra = r0 + mi * 16, rb = ra + 8;
            float2 v0 = { acc[mi][j][0] + b0v, acc[mi][j][1] + b1v };
            float2 v1 = { acc[mi][j][2] + b0v, acc[mi][j][3] + b1v };
            if (EPI == 1) {
                const float2 ra2 = *reinterpret_cast<const float2*>(
                    res + (size_t)ra * Nn + col);
                const float2 rb2 = *reinterpret_cast<const float2*>(
                    res + (size_t)rb * Nn + col);
                v0.x += ra2.x; v0.y += ra2.y; v1.x += rb2.x; v1.y += rb2.y;
            }
            if (EPI == 2) {
                v0.x = gelu_exact(v0.x); v0.y = gelu_exact(v0.y);
                v1.x = gelu_exact(v1.x); v1.y = gelu_exact(v1.y);
                __nv_bfloat16 h0, l0, h1, l1, h2, l2, h3, l3;
                splitbf(v0.x, h0, l0); splitbf(v0.y, h1, l1);
                splitbf(v1.x, h2, l2); splitbf(v1.y, h3, l3);
                *reinterpret_cast<uint32_t*>(Ch + (size_t)ra * Nn + col) = pck(h0, h1);
                *reinterpret_cast<uint32_t*>(Cl + (size_t)ra * Nn + col) = pck(l0, l1);
                *reinterpret_cast<uint32_t*>(Ch + (size_t)rb * Nn + col) = pck(h2, h3);
                *reinterpret_cast<uint32_t*>(Cl + (size_t)rb * Nn + col) = pck(l2, l3);
            } else {
                *reinterpret_cast<float2*>(Co + (size_t)ra * Nn + col) = v0;
                *reinterpret_cast<float2*>(Co + (size_t)rb * Nn + col) = v1;
            }
        }
    }
}

// ---------------- flash attention v2: bf16 inputs, cp.async staging ---------
#define APITCH 72
#define ATILE  (64 * APITCH * 2)        // 9216 B
#define QTILE  (128 * APITCH * 2)       // 18432 B
#define ASMEM  (QTILE + 2 * 2 * ATILE)  // 55296 B

__global__ __launch_bounds__(256) void flash_attn2_kernel(
    const __nv_bfloat16* __restrict__ q, const __nv_bfloat16* __restrict__ k,
    const __nv_bfloat16* __restrict__ v, __nv_bfloat16* __restrict__ oh,
    __nv_bfloat16* __restrict__ ol)
{
    extern __shared__ char shm[];
    const uint32_t sbase = smem_u32(shm);
    const uint32_t kvb0  = sbase + QTILE;

    const int t    = threadIdx.x;
    const int lane = t & 31;
    const int warp = t >> 5;
    const int b    = blockIdx.y >> 4;
    const int h    = blockIdx.y & 15;
    const int q0   = blockIdx.x * 128;
    const int wm   = warp * 16;

    // Q stage via cp.async (pre-scaled in postqkv)
    #pragma unroll
    for (int i = 0; i < 4; i++) {
        const int idx = i * 256 + t;
        const int row = idx >> 3, c = idx & 7;
        cp16(sbase + row * (APITCH * 2) + c * 16,
             q + (size_t)(b * NSEQ + q0 + row) * CDIM + h * HDIM + c * 8);
    }
    cpcommit();

    #define KV_ISSUE(kt, stg)                                                 \
        { const uint32_t sb = kvb0 + (uint32_t)(stg) * 2 * ATILE;             \
          _Pragma("unroll")                                                   \
          for (int i = 0; i < 2; i++) {                                       \
              const int idx = i * 256 + t;                                    \
              const int row = idx >> 3, c = idx & 7;                          \
              const size_t g = (size_t)(b * NSEQ + (kt) * 64 + row) * CDIM    \
                               + h * HDIM + c * 8;                            \
              const uint32_t d = sb + row * (APITCH * 2) + c * 16;            \
              cp16(d,         k + g);                                         \
              cp16(d + ATILE, v + g);                                         \
          } }

    KV_ISSUE(0, 0); cpcommit();
    cpwait1();          // Q group done
    __syncthreads();

    uint32_t qf[4][4];
    #pragma unroll
    for (int ks = 0; ks < 4; ks++)
        ldmat4(qf[ks], sbase + ((wm + (lane & 15)) * APITCH + ks * 16
                                + (lane >> 4) * 8) * 2);

    float m0 = -1e30f, m1 = -1e30f, l0 = 0.0f, l1 = 0.0f;
    float oa[8][4];
    #pragma unroll
    for (int j = 0; j < 8; j++)
        #pragma unroll
        for (int p = 0; p < 4; p++) oa[j][p] = 0.0f;

    const int NT = NSEQ / 64;
    for (int kt = 0; kt < NT; kt++) {
        if (kt + 1 < NT) { KV_ISSUE(kt + 1, (kt + 1) & 1); cpcommit(); cpwait1(); }
        else             { cpwait0(); }
        __syncthreads();

        const uint32_t kb = kvb0 + (uint32_t)(kt & 1) * 2 * ATILE;
        const uint32_t vb = kb + ATILE;

        float sc[8][4];
        #pragma unroll
        for (int j = 0; j < 8; j++)
            #pragma unroll
            for (int p = 0; p < 4; p++) sc[j][p] = 0.0f;

        #pragma unroll
        for (int ks = 0; ks < 4; ks++) {
            #pragma unroll
            for (int p = 0; p < 4; p++) {
                uint32_t r4[4];
                ldmat4(r4, kb + ((p * 16 + (lane & 7) + ((lane >> 4) << 3)) * APITCH
                                 + ks * 16 + ((lane >> 3) & 1) * 8) * 2);
                mma16816(sc[2*p],   qf[ks], r4[0], r4[1]);
                mma16816(sc[2*p+1], qf[ks], r4[2], r4[3]);
            }
        }

        float mx0 = sc[0][0], mx1 = sc[0][2];
        #pragma unroll
        for (int j = 0; j < 8; j++) {
            mx0 = fmaxf(mx0, fmaxf(sc[j][0], sc[j][1]));
            mx1 = fmaxf(mx1, fmaxf(sc[j][2], sc[j][3]));
        }
        mx0 = fmaxf(mx0, __shfl_xor_sync(0xffffffffu, mx0, 1));
        mx0 = fmaxf(mx0, __shfl_xor_sync(0xffffffffu, mx0, 2));
        mx1 = fmaxf(mx1, __shfl_xor_sync(0xffffffffu, mx1, 1));
        mx1 = fmaxf(mx1, __shfl_xor_sync(0xffffffffu, mx1, 2));

        const float mn0 = fmaxf(m0, mx0), mn1 = fmaxf(m1, mx1);
        const float cr0 = ex2f(m0 - mn0), cr1 = ex2f(m1 - mn1);
        m0 = mn0; m1 = mn1;

        float rs0 = 0.0f, rs1 = 0.0f;
        uint32_t pf[4][4];
        #pragma unroll
        for (int j = 0; j < 8; j++) {
            const float p0 = ex2f(sc[j][0] - mn0);
            const float p1 = ex2f(sc[j][1] - mn0);
            const float p2 = ex2f(sc[j][2] - mn1);
            const float p3 = ex2f(sc[j][3] - mn1);
            rs0 += p0 + p1; rs1 += p2 + p3;
            pf[j >> 1][(j & 1) * 2 + 0] = pck(__float2bfloat16(p0), __float2bfloat16(p1));
            pf[j >> 1][(j & 1) * 2 + 1] = pck(__float2bfloat16(p2), __float2bfloat16(p3));
        }
        rs0 += __shfl_xor_sync(0xffffffffu, rs0, 1);
        rs0 += __shfl_xor_sync(0xffffffffu, rs0, 2);
        rs1 += __shfl_xor_sync(0xffffffffu, rs1, 1);
        rs1 += __shfl_xor_sync(0xffffffffu, rs1, 2);
        l0 = l0 * cr0 + rs0;
        l1 = l1 * cr1 + rs1;

        #pragma unroll
        for (int j = 0; j < 8; j++) {
            oa[j][0] *= cr0; oa[j][1] *= cr0;
            oa[j][2] *= cr1; oa[j][3] *= cr1;
        }

        #pragma unroll
        for (int ks = 0; ks < 4; ks++) {
            #pragma unroll
            for (int p = 0; p < 4; p++) {
                uint32_t r4[4];
                ldmat4t(r4, vb + ((ks * 16 + (lane & 15)) * APITCH
                                  + p * 16 + ((lane >> 4) << 3)) * 2);
                mma16816(oa[2*p],   pf[ks], r4[0], r4[1]);
                mma16816(oa[2*p+1], pf[ks], r4[2], r4[3]);
            }
        }
        __syncthreads();
    }
    #undef KV_ISSUE

    const float iv0 = 1.0f / l0, iv1 = 1.0f / l1;
    const int ra = q0 + wm + (lane >> 2);
    const int rb = ra + 8;
    #pragma unroll
    for (int j = 0; j < 8; j++) {
        const int col = h * HDIM + j * 8 + (lane & 3) * 2;
        const float w0 = oa[j][0] * iv0, w1 = oa[j][1] * iv0;
        const float w2 = oa[j][2] * iv1, w3 = oa[j][3] * iv1;
        __nv_bfloat16 h0, l0b, h1, l1b, h2, l2b, h3, l3b;
        splitbf(w0, h0, l0b); splitbf(w1, h1, l1b);
        splitbf(w2, h2, l2b); splitbf(w3, h3, l3b);
        *reinterpret_cast<uint32_t*>(oh + (size_t)(b * NSEQ + ra) * CDIM + col) = pck(h0, h1);
        *reinterpret_cast<uint32_t*>(ol + (size_t)(b * NSEQ + ra) * CDIM + col) = pck(l0b, l1b);
        *reinterpret_cast<uint32_t*>(oh + (size_t)(b * NSEQ + rb) * CDIM + col) = pck(h2, h3);
        *reinterpret_cast<uint32_t*>(ol + (size_t)(b * NSEQ + rb) * CDIM + col) = pck(l2b, l3b);
    }
}

// ---------------- host orchestration ----------------------------------------
extern "C" void kernel_launch(void* const* d_in, const int* in_sizes, int n_in,
                              void* d_out, int out_size)
{
    const float* x      = (const float*)d_in[0];
    const float* wq     = (const float*)d_in[1];
    const float* bq     = (const float*)d_in[2];
    const float* wk     = (const float*)d_in[3];
    const float* bk     = (const float*)d_in[4];
    const float* wv     = (const float*)d_in[5];
    const float* bv     = (const float*)d_in[6];
    const float* wo     = (const float*)d_in[7];
    const float* bo     = (const float*)d_in[8];
    const float* scale1 = (const float*)d_in[9];
    const float* scale2 = (const float*)d_in[10];
    const float* w1     = (const float*)d_in[11];
    const float* b1     = (const float*)d_in[12];
    const float* w2     = (const float*)d_in[13];
    const float* b2     = (const float*)d_in[14];
    float* out = (float*)d_out;

    __nv_bfloat16 *p_xnh, *p_xnl, *p_qb, *p_kb, *p_vb, *p_ctxh, *p_ctxl;
    __nv_bfloat16 *p_xn2h, *p_xn2l, *p_hh, *p_hl;
    __nv_bfloat16 *p_wqkvh, *p_wqkvl, *p_woh, *p_wol, *p_w1h, *p_w1l, *p_w2h, *p_w2l;
    float *p_qkv, *p_x2, *p_bqkv;
    cudaGetSymbolAddress((void**)&p_xnh,  g_xnh);
    cudaGetSymbolAddress((void**)&p_xnl,  g_xnl);
    cudaGetSymbolAddress((void**)&p_qkv,  g_qkv);
    cudaGetSymbolAddress((void**)&p_qb,   g_qb);
    cudaGetSymbolAddress((void**)&p_kb,   g_kb);
    cudaGetSymbolAddress((void**)&p_vb,   g_vb);
    cudaGetSymbolAddress((void**)&p_ctxh, g_ctxh);
    cudaGetSymbolAddress((void**)&p_ctxl, g_ctxl);
    cudaGetSymbolAddress((void**)&p_x2,   g_x2);
    cudaGetSymbolAddress((void**)&p_xn2h, g_xn2h);
    cudaGetSymbolAddress((void**)&p_xn2l, g_xn2l);
    cudaGetSymbolAddress((void**)&p_hh,   g_hh);
    cudaGetSymbolAddress((void**)&p_hl,   g_hl);
    cudaGetSymbolAddress((void**)&p_wqkvh, g_wqkvh);
    cudaGetSymbolAddress((void**)&p_wqkvl, g_wqkvl);
    cudaGetSymbolAddress((void**)&p_woh,  g_woh);
    cudaGetSymbolAddress((void**)&p_wol,  g_wol);
    cudaGetSymbolAddress((void**)&p_w1h,  g_w1h);
    cudaGetSymbolAddress((void**)&p_w1l,  g_w1l);
    cudaGetSymbolAddress((void**)&p_w2h,  g_w2h);
    cudaGetSymbolAddress((void**)&p_w2l,  g_w2l);
    cudaGetSymbolAddress((void**)&p_bqkv, g_bqkv);

    cudaFuncSetAttribute(gemm2_kernel<0>,
                         cudaFuncAttributeMaxDynamicSharedMemorySize, GSMEM);
    cudaFuncSetAttribute(gemm2_kernel<1>,
                         cudaFuncAttributeMaxDynamicSharedMemorySize, GSMEM);
    cudaFuncSetAttribute(gemm2_kernel<2>,
                         cudaFuncAttributeMaxDynamicSharedMemorySize, GSMEM);
    cudaFuncSetAttribute(flash_attn2_kernel,
                         cudaFuncAttributeMaxDynamicSharedMemorySize, ASMEM);

    const dim3 tb(32, 8);

    // launch 0
    bias_concat_kernel<<<QKVN / 256, 256>>>(bq, bk, bv, p_bqkv);
    // launches 1-3: QKV weight transposes+split into concatenated buffer
    transpose_split_kernel<<<dim3(CDIM/32, CDIM/32), tb>>>(
        wq, p_wqkvh, p_wqkvl, CDIM, CDIM);
    transpose_split_kernel<<<dim3(CDIM/32, CDIM/32), tb>>>(
        wk, p_wqkvh + (size_t)CDIM*CDIM, p_wqkvl + (size_t)CDIM*CDIM, CDIM, CDIM);
    transpose_split_kernel<<<dim3(CDIM/32, CDIM/32), tb>>>(
        wv, p_wqkvh + (size_t)2*CDIM*CDIM, p_wqkvl + (size_t)2*CDIM*CDIM, CDIM, CDIM);
    // launch 4
    rmsnorm_split_kernel<<<MTOT, 256>>>(x, scale1, p_xnh, p_xnl);
    // launch 5: fused QKV GEMM  (profiled by ncu -s 5)
    gemm2_kernel<0><<<dim3(QKVN/128, MTOT/128), 256, GSMEM>>>(
        p_xnh, p_xnl, p_wqkvh, p_wqkvl, p_bqkv, nullptr,
        p_qkv, nullptr, nullptr, MTOT, QKVN, CDIM);
    // launch 6
    postqkv_kernel<<<dim3(MTOT*NHEAD/256, 3), 256>>>(p_qkv, p_qb, p_kb, p_vb);
    // launch 7
    flash_attn2_kernel<<<dim3(NSEQ/128, 2*NHEAD), 256, ASMEM>>>(
        p_qb, p_kb, p_vb, p_ctxh, p_ctxl);
    // launch 8
    transpose_split_kernel<<<dim3(CDIM/32, CDIM/32), tb>>>(wo, p_woh, p_wol, CDIM, CDIM);
    // launch 9: x2 = x + ctx@wo + bo
    gemm2_kernel<1><<<dim3(CDIM/128, MTOT/128), 256, GSMEM>>>(
        p_ctxh, p_ctxl, p_woh, p_wol, bo, x,
        p_x2, nullptr, nullptr, MTOT, CDIM, CDIM);
    // launch 10
    rmsnorm_split_kernel<<<MTOT, 256>>>(p_x2, scale2, p_xn2h, p_xn2l);
    // launch 11
    transpose_split_kernel<<<dim3(FFDIM/32, CDIM/32), tb>>>(w1, p_w1h, p_w1l, CDIM, FFDIM);
    // launch 12: h = gelu(xn2@w1 + b1) -> split bf16
    gemm2_kernel<2><<<dim3(FFDIM/128, MTOT/128), 256, GSMEM>>>(
        p_xn2h, p_xn2l, p_w1h, p_w1l, b1, nullptr,
        nullptr, p_hh, p_hl, MTOT, FFDIM, CDIM);
    // launch 13
    transpose_split_kernel<<<dim3(CDIM/32, FFDIM/32), tb>>>(w2, p_w2h, p_w2l, FFDIM, CDIM);
    // launch 14: out = x2 + h@w2 + b2
    gemm2_kernel<1><<<dim3(CDIM/128, MTOT/128), 256, GSMEM>>>(
        p_hh, p_hl, p_w2h, p_w2l, b2, p_x2,
        out, nullptr, nullptr, MTOT, CDIM, FFDIM);
}

// round 6
// speedup vs baseline: 6.4966x; 1.6906x over previous
#include <cuda_runtime.h>
#include <cuda_fp16.h>
#include <math.h>
#include <stdint.h>

// Problem dims (fixed): B=2, N=2048, C=1024, H=16, D=64, FF=4096
#define MTOT 4096
#define CDIM 1024
#define FFDIM 4096
#define NSEQ 2048
#define NHEAD 16
#define HDIM 64
#define QKVN 3072

// ---------------- scratch (no allocations -> __device__ globals) ------------
__device__ __half g_xn  [MTOT*CDIM];
__device__ float  g_qkv [MTOT*QKVN];
__device__ __half g_qb  [MTOT*CDIM], g_kb[MTOT*CDIM], g_vb[MTOT*CDIM];
__device__ __half g_ctx [MTOT*CDIM];
__device__ float  g_x2  [MTOT*CDIM];
__device__ __half g_xn2 [MTOT*CDIM];
__device__ __half g_h   [MTOT*FFDIM];
__device__ __half g_wqkv[QKVN*CDIM];
__device__ __half g_wo  [CDIM*CDIM];
__device__ __half g_w1  [FFDIM*CDIM];
__device__ __half g_w2  [CDIM*FFDIM];
__device__ float  g_bqkv[QKVN];

// ---------------- helpers ----------------------------------------------------
__device__ __forceinline__ uint32_t smem_u32(const void* p) {
    uint32_t a;
    asm("{ .reg .u64 t; cvta.to.shared.u64 t, %1; cvt.u32.u64 %0, t; }"
        : "=r"(a) : "l"(p));
    return a;
}
__device__ __forceinline__ void ldmat4(uint32_t (&r)[4], uint32_t addr) {
    asm volatile("ldmatrix.sync.aligned.m8n8.x4.shared.b16 {%0,%1,%2,%3}, [%4];"
                 : "=r"(r[0]), "=r"(r[1]), "=r"(r[2]), "=r"(r[3]) : "r"(addr));
}
__device__ __forceinline__ void ldmat4t(uint32_t (&r)[4], uint32_t addr) {
    asm volatile("ldmatrix.sync.aligned.m8n8.x4.trans.shared.b16 {%0,%1,%2,%3}, [%4];"
                 : "=r"(r[0]), "=r"(r[1]), "=r"(r[2]), "=r"(r[3]) : "r"(addr));
}
__device__ __forceinline__ void mma16816(float (&d)[4], const uint32_t (&a)[4],
                                         uint32_t b0, uint32_t b1) {
    asm volatile(
        "mma.sync.aligned.m16n8k16.row.col.f32.f16.f16.f32 "
        "{%0,%1,%2,%3}, {%4,%5,%6,%7}, {%8,%9}, {%0,%1,%2,%3};"
        : "+f"(d[0]), "+f"(d[1]), "+f"(d[2]), "+f"(d[3])
        : "r"(a[0]), "r"(a[1]), "r"(a[2]), "r"(a[3]), "r"(b0), "r"(b1));
}
__device__ __forceinline__ uint32_t pckh(__half a, __half b) {
    __half2 t(a, b);
    return *reinterpret_cast<uint32_t*>(&t);
}
__device__ __forceinline__ uint32_t pckf(float a, float b) {
    return pckh(__float2half(a), __float2half(b));
}
__device__ __forceinline__ float ex2f(float x) {
    float y;
    asm("ex2.approx.f32 %0, %1;" : "=f"(y) : "f"(x));
    return y;
}
__device__ __forceinline__ float gelu_exact(float x) {
    return 0.5f * x * (1.0f + erff(x * 0.7071067811865476f));
}
__device__ __forceinline__ void cp16(uint32_t d, const void* s) {
    asm volatile("cp.async.cg.shared.global [%0], [%1], 16;" :: "r"(d), "l"(s));
}
__device__ __forceinline__ void cpcommit() {
    asm volatile("cp.async.commit_group;" ::: "memory");
}
__device__ __forceinline__ void cpwait0() {
    asm volatile("cp.async.wait_group 0;" ::: "memory");
}
__device__ __forceinline__ void cpwait1() {
    asm volatile("cp.async.wait_group 1;" ::: "memory");
}

// ---------------- misc small kernels ----------------------------------------
__global__ void bias_concat_kernel(const float* bq, const float* bk,
                                   const float* bv, float* out)
{
    const int i = blockIdx.x * 256 + threadIdx.x;
    float v;
    if (i < 1024)      v = bq[i];
    else if (i < 2048) v = bk[i - 1024];
    else               v = bv[i - 2048];
    out[i] = v;
}

// w [R,Cc] fp32 -> wT [Cc,R] fp16
__global__ __launch_bounds__(256) void transpose_h_kernel(
    const float* __restrict__ in, __half* __restrict__ o, int R, int Cc)
{
    __shared__ float ts[32][33];
    const int tx = threadIdx.x, ty = threadIdx.y;
    const int c0 = blockIdx.x * 32, r0 = blockIdx.y * 32;
    #pragma unroll
    for (int i = 0; i < 4; i++)
        ts[ty + 8*i][tx] = in[(size_t)(r0 + ty + 8*i) * Cc + c0 + tx];
    __syncthreads();
    #pragma unroll
    for (int i = 0; i < 4; i++)
        o[(size_t)(c0 + ty + 8*i) * R + r0 + tx] = __float2half(ts[tx][ty + 8*i]);
}

// RMSNorm -> fp16
__global__ __launch_bounds__(256) void rmsnorm_h_kernel(
    const float* __restrict__ x, const float* __restrict__ scale,
    __half* __restrict__ o)
{
    __shared__ float red[8];
    const int row = blockIdx.x;
    const int t   = threadIdx.x;
    const float* xr = x + (size_t)row * CDIM;

    float4 v = *reinterpret_cast<const float4*>(xr + t * 4);
    float ss = v.x * v.x + v.y * v.y + v.z * v.z + v.w * v.w;
    #pragma unroll
    for (int of = 16; of > 0; of >>= 1) ss += __shfl_xor_sync(0xffffffffu, ss, of);
    if ((t & 31) == 0) red[t >> 5] = ss;
    __syncthreads();
    if (t < 8) {
        float s2 = red[t];
        #pragma unroll
        for (int of = 4; of > 0; of >>= 1) s2 += __shfl_xor_sync(0xffu, s2, of);
        if (t == 0) red[0] = s2;
    }
    __syncthreads();
    const float norm = sqrtf(red[0]);
    const float inv  = 1.0f / (norm * 0.03125f + 1e-8f);

    float4 sc = *reinterpret_cast<const float4*>(scale + t * 4);
    uint2 w;
    w.x = pckf(v.x * sc.x * inv, v.y * sc.y * inv);
    w.y = pckf(v.z * sc.z * inv, v.w * sc.w * inv);
    *reinterpret_cast<uint2*>(o + (size_t)row * CDIM + t * 4) = w;
}

// post-QKV: rotary on q (then scale), rotary on k, copy v; fp32 -> fp16
__global__ __launch_bounds__(256) void postqkv_kernel(
    const float* __restrict__ qkv, __half* __restrict__ qb,
    __half* __restrict__ kb, __half* __restrict__ vb)
{
    const int id  = blockIdx.x * 256 + threadIdx.x;
    const int sec = blockIdx.y;
    const int m   = id >> 4;
    const int h   = id & 15;
    const float* src = qkv + (size_t)m * QKVN + sec * 1024 + h * HDIM;
    __half* dst = (sec == 0 ? qb : sec == 1 ? kb : vb)
                  + (size_t)m * CDIM + h * HDIM;

    float v[HDIM];
    #pragma unroll
    for (int i = 0; i < HDIM / 4; i++) {
        float4 f = *reinterpret_cast<const float4*>(src + i * 4);
        v[i*4+0] = f.x; v[i*4+1] = f.y; v[i*4+2] = f.z; v[i*4+3] = f.w;
    }
    const float cscale = 0.125f * 1.4426950408889634f;
    float o[HDIM];
    if (sec == 2) {
        #pragma unroll
        for (int d = 0; d < HDIM; d++) o[d] = v[d];
    } else {
        #pragma unroll
        for (int d = 0; d < HDIM; d++)
            o[d] = v[d] - v[(d + HDIM - 1) & (HDIM - 1)];
        if (sec == 0) {
            #pragma unroll
            for (int d = 0; d < HDIM; d++) o[d] *= cscale;
        }
    }
    #pragma unroll
    for (int i = 0; i < HDIM / 8; i++) {
        uint4 w;
        w.x = pckf(o[i*8+0], o[i*8+1]);
        w.y = pckf(o[i*8+2], o[i*8+3]);
        w.z = pckf(o[i*8+4], o[i*8+5]);
        w.w = pckf(o[i*8+6], o[i*8+7]);
        *reinterpret_cast<uint4*>(dst + i * 8) = w;
    }
}

// ---------------- GEMM v3: single fp16, cp.async pipeline -------------------
// D[M,N] = A[M,K] @ B^T[N,K].  EPI: 0 bias->fp32 ; 1 bias+res->fp32 ;
//                              2 bias+gelu->fp16
#define PITCH 40
#define TILEB (128 * PITCH * 2)     // 10240 B
#define STAGEB (2 * TILEB)          // 20480 B (A + B)
#define GSMEM (2 * STAGEB)          // 40960 B

template <int EPI>
__global__ __launch_bounds__(256, 2) void gemm3_kernel(
    const __half* __restrict__ A, const __half* __restrict__ Bw,
    const float* __restrict__ bias, const float* __restrict__ res,
    float* __restrict__ Co, __half* __restrict__ Ch, int M, int Nn, int K)
{
    extern __shared__ char sm[];
    const uint32_t sbase = smem_u32(sm);

    const int t    = threadIdx.x;
    const int lane = t & 31;
    const int warp = t >> 5;
    const int wm   = (warp & 3) * 32;
    const int wn   = (warp >> 2) * 64;
    const int bm   = blockIdx.y * 128;
    const int bn   = blockIdx.x * 128;

    const uint32_t aoffA =
        ((wm + (lane & 15)) * PITCH + ((lane >> 4) * 8)) * 2;
    const uint32_t aoffB =
        ((wn + (lane & 7) + ((lane >> 4) << 3)) * PITCH + (((lane >> 3) & 1) * 8)) * 2;

    float acc[2][8][4];
    #pragma unroll
    for (int mi = 0; mi < 2; mi++)
        #pragma unroll
        for (int j = 0; j < 8; j++)
            #pragma unroll
            for (int q = 0; q < 4; q++) acc[mi][j][q] = 0.0f;

    const int KT = K / 32;

    #define G_ISSUE(kt, stg)                                                  \
        { const uint32_t sb = sbase + (uint32_t)(stg) * STAGEB;               \
          const int row = t >> 1, c = t & 1;                                  \
          const uint32_t d = sb + row * (PITCH * 2) + c * 32;                 \
          const size_t ga = (size_t)(bm + row) * K + (kt) * 32 + c * 16;      \
          const size_t gb = (size_t)(bn + row) * K + (kt) * 32 + c * 16;      \
          cp16(d,              A  + ga);                                      \
          cp16(d + 16,         A  + ga + 8);                                  \
          cp16(d + TILEB,      Bw + gb);                                      \
          cp16(d + TILEB + 16, Bw + gb + 8);                                  \
        }

    G_ISSUE(0, 0); cpcommit();

    for (int kt = 0; kt < KT; kt++) {
        if (kt + 1 < KT) { G_ISSUE(kt + 1, (kt + 1) & 1); cpcommit(); cpwait1(); }
        else             { cpwait0(); }
        __syncthreads();

        const uint32_t sA = sbase + (uint32_t)(kt & 1) * STAGEB;
        const uint32_t sB = sA + TILEB;

        #pragma unroll
        for (int ks = 0; ks < 2; ks++) {
            uint32_t af[2][4];
            ldmat4(af[0], sA + aoffA + ks * 32);
            ldmat4(af[1], sA + aoffA + 16 * PITCH * 2 + ks * 32);
            #pragma unroll
            for (int p = 0; p < 4; p++) {
                uint32_t bf4[4];
                ldmat4(bf4, sB + aoffB + p * 16 * PITCH * 2 + ks * 32);
                #pragma unroll
                for (int mi = 0; mi < 2; mi++) {
                    mma16816(acc[mi][2*p],   af[mi], bf4[0], bf4[1]);
                    mma16816(acc[mi][2*p+1], af[mi], bf4[2], bf4[3]);
                }
            }
        }
        __syncthreads();
    }
    #undef G_ISSUE

    const int r0 = bm + wm + (lane >> 2);
    const int cb = bn + wn + (lane & 3) * 2;
    #pragma unroll
    for (int mi = 0; mi < 2; mi++) {
        #pragma unroll
        for (int j = 0; j < 8; j++) {
            const int col = cb + j * 8;
            const float b0v = bias[col], b1v = bias[col + 1];
            const int ra = r0 + mi * 16, rb = ra + 8;
            float2 v0 = { acc[mi][j][0] + b0v, acc[mi][j][1] + b1v };
            float2 v1 = { acc[mi][j][2] + b0v, acc[mi][j][3] + b1v };
            if (EPI == 1) {
                const float2 ra2 = *reinterpret_cast<const float2*>(
                    res + (size_t)ra * Nn + col);
                const float2 rb2 = *reinterpret_cast<const float2*>(
                    res + (size_t)rb * Nn + col);
                v0.x += ra2.x; v0.y += ra2.y; v1.x += rb2.x; v1.y += rb2.y;
            }
            if (EPI == 2) {
                *reinterpret_cast<uint32_t*>(Ch + (size_t)ra * Nn + col) =
                    pckf(gelu_exact(v0.x), gelu_exact(v0.y));
                *reinterpret_cast<uint32_t*>(Ch + (size_t)rb * Nn + col) =
                    pckf(gelu_exact(v1.x), gelu_exact(v1.y));
            } else {
                *reinterpret_cast<float2*>(Co + (size_t)ra * Nn + col) = v0;
                *reinterpret_cast<float2*>(Co + (size_t)rb * Nn + col) = v1;
            }
        }
    }
}

// ---------------- flash attention v3: fp16, cp.async staging ----------------
#define APITCH 72
#define ATILE  (64 * APITCH * 2)        // 9216 B
#define QTILE  (128 * APITCH * 2)       // 18432 B
#define ASMEM  (QTILE + 2 * 2 * ATILE)  // 55296 B

__global__ __launch_bounds__(256) void flash_attn3_kernel(
    const __half* __restrict__ q, const __half* __restrict__ k,
    const __half* __restrict__ v, __half* __restrict__ o)
{
    extern __shared__ char shm[];
    const uint32_t sbase = smem_u32(shm);
    const uint32_t kvb0  = sbase + QTILE;

    const int t    = threadIdx.x;
    const int lane = t & 31;
    const int warp = t >> 5;
    const int b    = blockIdx.y >> 4;
    const int h    = blockIdx.y & 15;
    const int q0   = blockIdx.x * 128;
    const int wm   = warp * 16;

    #pragma unroll
    for (int i = 0; i < 4; i++) {
        const int idx = i * 256 + t;
        const int row = idx >> 3, c = idx & 7;
        cp16(sbase + row * (APITCH * 2) + c * 16,
             q + (size_t)(b * NSEQ + q0 + row) * CDIM + h * HDIM + c * 8);
    }
    cpcommit();

    #define KV_ISSUE(kt, stg)                                                 \
        { const uint32_t sb = kvb0 + (uint32_t)(stg) * 2 * ATILE;             \
          _Pragma("unroll")                                                   \
          for (int i = 0; i < 2; i++) {                                       \
              const int idx = i * 256 + t;                                    \
              const int row = idx >> 3, c = idx & 7;                          \
              const size_t g = (size_t)(b * NSEQ + (kt) * 64 + row) * CDIM    \
                               + h * HDIM + c * 8;                            \
              const uint32_t d = sb + row * (APITCH * 2) + c * 16;            \
              cp16(d,         k + g);                                         \
              cp16(d + ATILE, v + g);                                         \
          } }

    KV_ISSUE(0, 0); cpcommit();
    cpwait1();
    __syncthreads();

    uint32_t qf[4][4];
    #pragma unroll
    for (int ks = 0; ks < 4; ks++)
        ldmat4(qf[ks], sbase + ((wm + (lane & 15)) * APITCH + ks * 16
                                + (lane >> 4) * 8) * 2);

    float m0 = -1e30f, m1 = -1e30f, l0 = 0.0f, l1 = 0.0f;
    float oa[8][4];
    #pragma unroll
    for (int j = 0; j < 8; j++)
        #pragma unroll
        for (int p = 0; p < 4; p++) oa[j][p] = 0.0f;

    const int NT = NSEQ / 64;
    for (int kt = 0; kt < NT; kt++) {
        if (kt + 1 < NT) { KV_ISSUE(kt + 1, (kt + 1) & 1); cpcommit(); cpwait1(); }
        else             { cpwait0(); }
        __syncthreads();

        const uint32_t kb = kvb0 + (uint32_t)(kt & 1) * 2 * ATILE;
        const uint32_t vb = kb + ATILE;

        float sc[8][4];
        #pragma unroll
        for (int j = 0; j < 8; j++)
            #pragma unroll
            for (int p = 0; p < 4; p++) sc[j][p] = 0.0f;

        #pragma unroll
        for (int ks = 0; ks < 4; ks++) {
            #pragma unroll
            for (int p = 0; p < 4; p++) {
                uint32_t r4[4];
                ldmat4(r4, kb + ((p * 16 + (lane & 7) + ((lane >> 4) << 3)) * APITCH
                                 + ks * 16 + ((lane >> 3) & 1) * 8) * 2);
                mma16816(sc[2*p],   qf[ks], r4[0], r4[1]);
                mma16816(sc[2*p+1], qf[ks], r4[2], r4[3]);
            }
        }

        float mx0 = sc[0][0], mx1 = sc[0][2];
        #pragma unroll
        for (int j = 0; j < 8; j++) {
            mx0 = fmaxf(mx0, fmaxf(sc[j][0], sc[j][1]));
            mx1 = fmaxf(mx1, fmaxf(sc[j][2], sc[j][3]));
        }
        mx0 = fmaxf(mx0, __shfl_xor_sync(0xffffffffu, mx0, 1));
        mx0 = fmaxf(mx0, __shfl_xor_sync(0xffffffffu, mx0, 2));
        mx1 = fmaxf(mx1, __shfl_xor_sync(0xffffffffu, mx1, 1));
        mx1 = fmaxf(mx1, __shfl_xor_sync(0xffffffffu, mx1, 2));

        const float mn0 = fmaxf(m0, mx0), mn1 = fmaxf(m1, mx1);
        const float cr0 = ex2f(m0 - mn0), cr1 = ex2f(m1 - mn1);
        m0 = mn0; m1 = mn1;

        float rs0 = 0.0f, rs1 = 0.0f;
        uint32_t pf[4][4];
        #pragma unroll
        for (int j = 0; j < 8; j++) {
            const float p0 = ex2f(sc[j][0] - mn0);
            const float p1 = ex2f(sc[j][1] - mn0);
            const float p2 = ex2f(sc[j][2] - mn1);
            const float p3 = ex2f(sc[j][3] - mn1);
            rs0 += p0 + p1; rs1 += p2 + p3;
            pf[j >> 1][(j & 1) * 2 + 0] = pckf(p0, p1);
            pf[j >> 1][(j & 1) * 2 + 1] = pckf(p2, p3);
        }
        rs0 += __shfl_xor_sync(0xffffffffu, rs0, 1);
        rs0 += __shfl_xor_sync(0xffffffffu, rs0, 2);
        rs1 += __shfl_xor_sync(0xffffffffu, rs1, 1);
        rs1 += __shfl_xor_sync(0xffffffffu, rs1, 2);
        l0 = l0 * cr0 + rs0;
        l1 = l1 * cr1 + rs1;

        #pragma unroll
        for (int j = 0; j < 8; j++) {
            oa[j][0] *= cr0; oa[j][1] *= cr0;
            oa[j][2] *= cr1; oa[j][3] *= cr1;
        }

        #pragma unroll
        for (int ks = 0; ks < 4; ks++) {
            #pragma unroll
            for (int p = 0; p < 4; p++) {
                uint32_t r4[4];
                ldmat4t(r4, vb + ((ks * 16 + (lane & 15)) * APITCH
                                  + p * 16 + ((lane >> 4) << 3)) * 2);
                mma16816(oa[2*p],   pf[ks], r4[0], r4[1]);
                mma16816(oa[2*p+1], pf[ks], r4[2], r4[3]);
            }
        }
        __syncthreads();
    }
    #undef KV_ISSUE

    const float iv0 = 1.0f / l0, iv1 = 1.0f / l1;
    const int ra = q0 + wm + (lane >> 2);
    const int rb = ra + 8;
    #pragma unroll
    for (int j = 0; j < 8; j++) {
        const int col = h * HDIM + j * 8 + (lane & 3) * 2;
        *reinterpret_cast<uint32_t*>(o + (size_t)(b * NSEQ + ra) * CDIM + col) =
            pckf(oa[j][0] * iv0, oa[j][1] * iv0);
        *reinterpret_cast<uint32_t*>(o + (size_t)(b * NSEQ + rb) * CDIM + col) =
            pckf(oa[j][2] * iv1, oa[j][3] * iv1);
    }
}

// ---------------- host orchestration ----------------------------------------
extern "C" void kernel_launch(void* const* d_in, const int* in_sizes, int n_in,
                              void* d_out, int out_size)
{
    const float* x      = (const float*)d_in[0];
    const float* wq     = (const float*)d_in[1];
    const float* bq     = (const float*)d_in[2];
    const float* wk     = (const float*)d_in[3];
    const float* bk     = (const float*)d_in[4];
    const float* wv     = (const float*)d_in[5];
    const float* bv     = (const float*)d_in[6];
    const float* wo     = (const float*)d_in[7];
    const float* bo     = (const float*)d_in[8];
    const float* scale1 = (const float*)d_in[9];
    const float* scale2 = (const float*)d_in[10];
    const float* w1     = (const float*)d_in[11];
    const float* b1     = (const float*)d_in[12];
    const float* w2     = (const float*)d_in[13];
    const float* b2     = (const float*)d_in[14];
    float* out = (float*)d_out;

    __half *p_xn, *p_qb, *p_kb, *p_vb, *p_ctx, *p_xn2, *p_h;
    __half *p_wqkv, *p_wo, *p_w1, *p_w2;
    float *p_qkv, *p_x2, *p_bqkv;
    cudaGetSymbolAddress((void**)&p_xn,   g_xn);
    cudaGetSymbolAddress((void**)&p_qkv,  g_qkv);
    cudaGetSymbolAddress((void**)&p_qb,   g_qb);
    cudaGetSymbolAddress((void**)&p_kb,   g_kb);
    cudaGetSymbolAddress((void**)&p_vb,   g_vb);
    cudaGetSymbolAddress((void**)&p_ctx,  g_ctx);
    cudaGetSymbolAddress((void**)&p_x2,   g_x2);
    cudaGetSymbolAddress((void**)&p_xn2,  g_xn2);
    cudaGetSymbolAddress((void**)&p_h,    g_h);
    cudaGetSymbolAddress((void**)&p_wqkv, g_wqkv);
    cudaGetSymbolAddress((void**)&p_wo,   g_wo);
    cudaGetSymbolAddress((void**)&p_w1,   g_w1);
    cudaGetSymbolAddress((void**)&p_w2,   g_w2);
    cudaGetSymbolAddress((void**)&p_bqkv, g_bqkv);

    cudaFuncSetAttribute(gemm3_kernel<0>,
                         cudaFuncAttributeMaxDynamicSharedMemorySize, GSMEM);
    cudaFuncSetAttribute(gemm3_kernel<1>,
                         cudaFuncAttributeMaxDynamicSharedMemorySize, GSMEM);
    cudaFuncSetAttribute(gemm3_kernel<2>,
                         cudaFuncAttributeMaxDynamicSharedMemorySize, GSMEM);
    cudaFuncSetAttribute(flash_attn3_kernel,
                         cudaFuncAttributeMaxDynamicSharedMemorySize, ASMEM);

    const dim3 tb(32, 8);

    bias_concat_kernel<<<QKVN / 256, 256>>>(bq, bk, bv, p_bqkv);
    transpose_h_kernel<<<dim3(CDIM/32, CDIM/32), tb>>>(wq, p_wqkv, CDIM, CDIM);
    transpose_h_kernel<<<dim3(CDIM/32, CDIM/32), tb>>>(
        wk, p_wqkv + (size_t)CDIM*CDIM, CDIM, CDIM);
    transpose_h_kernel<<<dim3(CDIM/32, CDIM/32), tb>>>(
        wv, p_wqkv + (size_t)2*CDIM*CDIM, CDIM, CDIM);
    rmsnorm_h_kernel<<<MTOT, 256>>>(x, scale1, p_xn);
    // launch 5: fused QKV GEMM (ncu -s 5 lands here)
    gemm3_kernel<0><<<dim3(QKVN/128, MTOT/128), 256, GSMEM>>>(
        p_xn, p_wqkv, p_bqkv, nullptr, p_qkv, nullptr, MTOT, QKVN, CDIM);
    postqkv_kernel<<<dim3(MTOT*NHEAD/256, 3), 256>>>(p_qkv, p_qb, p_kb, p_vb);
    flash_attn3_kernel<<<dim3(NSEQ/128, 2*NHEAD), 256, ASMEM>>>(
        p_qb, p_kb, p_vb, p_ctx);
    transpose_h_kernel<<<dim3(CDIM/32, CDIM/32), tb>>>(wo, p_wo, CDIM, CDIM);
    gemm3_kernel<1><<<dim3(CDIM/128, MTOT/128), 256, GSMEM>>>(
        p_ctx, p_wo, bo, x, p_x2, nullptr, MTOT, CDIM, CDIM);
    rmsnorm_h_kernel<<<MTOT, 256>>>(p_x2, scale2, p_xn2);
    transpose_h_kernel<<<dim3(FFDIM/32, CDIM/32), tb>>>(w1, p_w1, CDIM, FFDIM);
    gemm3_kernel<2><<<dim3(FFDIM/128, MTOT/128), 256, GSMEM>>>(
        p_xn2, p_w1, b1, nullptr, nullptr, p_h, MTOT, FFDIM, CDIM);
    transpose_h_kernel<<<dim3(CDIM/32, FFDIM/32), tb>>>(w2, p_w2, FFDIM, CDIM);
    gemm3_kernel<1><<<dim3(CDIM/128, MTOT/128), 256, GSMEM>>>(
        p_h, p_w2, b2, p_x2, out, nullptr, MTOT, CDIM, FFDIM);
}

// round 7
// speedup vs baseline: 7.4391x; 1.1451x over previous
#include <cuda_runtime.h>
#include <cuda_fp16.h>
#include <math.h>
#include <stdint.h>

// Problem dims (fixed): B=2, N=2048, C=1024, H=16, D=64, FF=4096
#define MTOT 4096
#define CDIM 1024
#define FFDIM 4096
#define NSEQ 2048
#define NHEAD 16
#define HDIM 64
#define QKVN 3072

// ---------------- scratch (no allocations -> __device__ globals) ------------
__device__ __half g_xn  [MTOT*CDIM];
__device__ __half g_qkvh[MTOT*QKVN];
__device__ __half g_qb  [MTOT*CDIM], g_kb[MTOT*CDIM], g_vb[MTOT*CDIM];
__device__ __half g_ctx [MTOT*CDIM];
__device__ float  g_x2  [MTOT*CDIM];
__device__ __half g_xn2 [MTOT*CDIM];
__device__ __half g_h   [MTOT*FFDIM];
__device__ __half g_wqkv[QKVN*CDIM];
__device__ __half g_wo  [CDIM*CDIM];
__device__ __half g_w1  [FFDIM*CDIM];
__device__ __half g_w2  [CDIM*FFDIM];
__device__ float  g_bqkv[QKVN];

// ---------------- helpers ----------------------------------------------------
__device__ __forceinline__ uint32_t smem_u32(const void* p) {
    uint32_t a;
    asm("{ .reg .u64 t; cvta.to.shared.u64 t, %1; cvt.u32.u64 %0, t; }"
        : "=r"(a) : "l"(p));
    return a;
}
__device__ __forceinline__ void ldmat4(uint32_t (&r)[4], uint32_t addr) {
    asm volatile("ldmatrix.sync.aligned.m8n8.x4.shared.b16 {%0,%1,%2,%3}, [%4];"
                 : "=r"(r[0]), "=r"(r[1]), "=r"(r[2]), "=r"(r[3]) : "r"(addr));
}
__device__ __forceinline__ void ldmat4t(uint32_t (&r)[4], uint32_t addr) {
    asm volatile("ldmatrix.sync.aligned.m8n8.x4.trans.shared.b16 {%0,%1,%2,%3}, [%4];"
                 : "=r"(r[0]), "=r"(r[1]), "=r"(r[2]), "=r"(r[3]) : "r"(addr));
}
__device__ __forceinline__ void mma16816(float (&d)[4], const uint32_t (&a)[4],
                                         uint32_t b0, uint32_t b1) {
    asm volatile(
        "mma.sync.aligned.m16n8k16.row.col.f32.f16.f16.f32 "
        "{%0,%1,%2,%3}, {%4,%5,%6,%7}, {%8,%9}, {%0,%1,%2,%3};"
        : "+f"(d[0]), "+f"(d[1]), "+f"(d[2]), "+f"(d[3])
        : "r"(a[0]), "r"(a[1]), "r"(a[2]), "r"(a[3]), "r"(b0), "r"(b1));
}
__device__ __forceinline__ uint32_t pckh(__half a, __half b) {
    __half2 t(a, b);
    return *reinterpret_cast<uint32_t*>(&t);
}
__device__ __forceinline__ uint32_t pckf(float a, float b) {
    return pckh(__float2half(a), __float2half(b));
}
__device__ __forceinline__ float ex2f(float x) {
    float y;
    asm("ex2.approx.f32 %0, %1;" : "=f"(y) : "f"(x));
    return y;
}
__device__ __forceinline__ float gelu_exact(float x) {
    return 0.5f * x * (1.0f + erff(x * 0.7071067811865476f));
}
__device__ __forceinline__ void cp16(uint32_t d, const void* s) {
    asm volatile("cp.async.cg.shared.global [%0], [%1], 16;" :: "r"(d), "l"(s));
}
__device__ __forceinline__ void cpcommit() {
    asm volatile("cp.async.commit_group;" ::: "memory");
}
__device__ __forceinline__ void cpwait0() {
    asm volatile("cp.async.wait_group 0;" ::: "memory");
}
__device__ __forceinline__ void cpwait1() {
    asm volatile("cp.async.wait_group 1;" ::: "memory");
}
__device__ __forceinline__ void cpwait2() {
    asm volatile("cp.async.wait_group 2;" ::: "memory");
}

// ---------------- misc small kernels ----------------------------------------
__global__ void bias_concat_kernel(const float* bq, const float* bk,
                                   const float* bv, float* out)
{
    const int i = blockIdx.x * 256 + threadIdx.x;
    float v;
    if (i < 1024)      v = bq[i];
    else if (i < 2048) v = bk[i - 1024];
    else               v = bv[i - 2048];
    out[i] = v;
}

__global__ __launch_bounds__(256) void transpose_h_kernel(
    const float* __restrict__ in, __half* __restrict__ o, int R, int Cc)
{
    __shared__ float ts[32][33];
    const int tx = threadIdx.x, ty = threadIdx.y;
    const int c0 = blockIdx.x * 32, r0 = blockIdx.y * 32;
    #pragma unroll
    for (int i = 0; i < 4; i++)
        ts[ty + 8*i][tx] = in[(size_t)(r0 + ty + 8*i) * Cc + c0 + tx];
    __syncthreads();
    #pragma unroll
    for (int i = 0; i < 4; i++)
        o[(size_t)(c0 + ty + 8*i) * R + r0 + tx] = __float2half(ts[tx][ty + 8*i]);
}

__global__ __launch_bounds__(256) void rmsnorm_h_kernel(
    const float* __restrict__ x, const float* __restrict__ scale,
    __half* __restrict__ o)
{
    __shared__ float red[8];
    const int row = blockIdx.x;
    const int t   = threadIdx.x;
    const float* xr = x + (size_t)row * CDIM;

    float4 v = *reinterpret_cast<const float4*>(xr + t * 4);
    float ss = v.x * v.x + v.y * v.y + v.z * v.z + v.w * v.w;
    #pragma unroll
    for (int of = 16; of > 0; of >>= 1) ss += __shfl_xor_sync(0xffffffffu, ss, of);
    if ((t & 31) == 0) red[t >> 5] = ss;
    __syncthreads();
    if (t < 8) {
        float s2 = red[t];
        #pragma unroll
        for (int of = 4; of > 0; of >>= 1) s2 += __shfl_xor_sync(0xffu, s2, of);
        if (t == 0) red[0] = s2;
    }
    __syncthreads();
    const float norm = sqrtf(red[0]);
    const float inv  = 1.0f / (norm * 0.03125f + 1e-8f);

    float4 sc = *reinterpret_cast<const float4*>(scale + t * 4);
    uint2 w;
    w.x = pckf(v.x * sc.x * inv, v.y * sc.y * inv);
    w.y = pckf(v.z * sc.z * inv, v.w * sc.w * inv);
    *reinterpret_cast<uint2*>(o + (size_t)row * CDIM + t * 4) = w;
}

// post-QKV (fp16 in): rotary q (+scale), rotary k, copy v
__global__ __launch_bounds__(256) void postqkv_kernel(
    const __half* __restrict__ qkv, __half* __restrict__ qb,
    __half* __restrict__ kb, __half* __restrict__ vb)
{
    const int id  = blockIdx.x * 256 + threadIdx.x;
    const int sec = blockIdx.y;
    const int m   = id >> 4;
    const int h   = id & 15;
    const __half* src = qkv + (size_t)m * QKVN + sec * 1024 + h * HDIM;
    __half* dst = (sec == 0 ? qb : sec == 1 ? kb : vb)
                  + (size_t)m * CDIM + h * HDIM;

    float v[HDIM];
    #pragma unroll
    for (int i = 0; i < HDIM / 8; i++) {
        uint4 w = *reinterpret_cast<const uint4*>(src + i * 8);
        const __half2* hp = reinterpret_cast<const __half2*>(&w);
        #pragma unroll
        for (int p = 0; p < 4; p++) {
            float2 f = __half22float2(hp[p]);
            v[i*8 + p*2 + 0] = f.x;
            v[i*8 + p*2 + 1] = f.y;
        }
    }
    const float cscale = 0.125f * 1.4426950408889634f;
    float o[HDIM];
    if (sec == 2) {
        #pragma unroll
        for (int d = 0; d < HDIM; d++) o[d] = v[d];
    } else {
        #pragma unroll
        for (int d = 0; d < HDIM; d++)
            o[d] = v[d] - v[(d + HDIM - 1) & (HDIM - 1)];
        if (sec == 0) {
            #pragma unroll
            for (int d = 0; d < HDIM; d++) o[d] *= cscale;
        }
    }
    #pragma unroll
    for (int i = 0; i < HDIM / 8; i++) {
        uint4 w;
        w.x = pckf(o[i*8+0], o[i*8+1]);
        w.y = pckf(o[i*8+2], o[i*8+3]);
        w.z = pckf(o[i*8+4], o[i*8+5]);
        w.w = pckf(o[i*8+6], o[i*8+7]);
        *reinterpret_cast<uint4*>(dst + i * 8) = w;
    }
}

// ---------------- GEMM v4: fp16, 3-stage cp.async, one sync/kt --------------
// EPI: 0 bias->fp32 ; 1 bias+res->fp32 ; 2 bias+gelu->fp16 ; 3 bias->fp16
#define PITCH 40
#define TILEB (128 * PITCH * 2)     // 10240 B
#define STAGEB (2 * TILEB)          // 20480 B (A + B)
#define GSMEM (3 * STAGEB)          // 61440 B

template <int EPI>
__global__ __launch_bounds__(256, 2) void gemm4_kernel(
    const __half* __restrict__ A, const __half* __restrict__ Bw,
    const float* __restrict__ bias, const float* __restrict__ res,
    float* __restrict__ Co, __half* __restrict__ Ch, int M, int Nn, int K)
{
    extern __shared__ char sm[];
    const uint32_t sbase = smem_u32(sm);

    const int t    = threadIdx.x;
    const int lane = t & 31;
    const int warp = t >> 5;
    const int wm   = (warp & 3) * 32;
    const int wn   = (warp >> 2) * 64;
    const int bm   = blockIdx.y * 128;
    const int bn   = blockIdx.x * 128;

    const uint32_t aoffA =
        ((wm + (lane & 15)) * PITCH + ((lane >> 4) * 8)) * 2;
    const uint32_t aoffB =
        ((wn + (lane & 7) + ((lane >> 4) << 3)) * PITCH + (((lane >> 3) & 1) * 8)) * 2;

    float acc[2][8][4];
    #pragma unroll
    for (int mi = 0; mi < 2; mi++)
        #pragma unroll
        for (int j = 0; j < 8; j++)
            #pragma unroll
            for (int q = 0; q < 4; q++) acc[mi][j][q] = 0.0f;

    const int KT = K / 32;

    #define G_ISSUE(kt, stg)                                                  \
        { const uint32_t sb = sbase + (uint32_t)(stg) * STAGEB;               \
          const int row = t >> 1, c = t & 1;                                  \
          const uint32_t d = sb + row * (PITCH * 2) + c * 32;                 \
          const size_t ga = (size_t)(bm + row) * K + (kt) * 32 + c * 16;      \
          const size_t gb = (size_t)(bn + row) * K + (kt) * 32 + c * 16;      \
          cp16(d,              A  + ga);                                      \
          cp16(d + 16,         A  + ga + 8);                                  \
          cp16(d + TILEB,      Bw + gb);                                      \
          cp16(d + TILEB + 16, Bw + gb + 8);                                  \
        }

    G_ISSUE(0, 0); cpcommit();
    G_ISSUE(1, 1); cpcommit();

    int stg = 0;
    for (int kt = 0; kt < KT; kt++) {
        if (kt + 1 < KT) cpwait1(); else cpwait0();
        __syncthreads();

        const uint32_t sA = sbase + (uint32_t)stg * STAGEB;
        const uint32_t sB = sA + TILEB;

        #pragma unroll
        for (int ks = 0; ks < 2; ks++) {
            uint32_t af[2][4];
            ldmat4(af[0], sA + aoffA + ks * 32);
            ldmat4(af[1], sA + aoffA + 16 * PITCH * 2 + ks * 32);
            #pragma unroll
            for (int p = 0; p < 4; p++) {
                uint32_t bf4[4];
                ldmat4(bf4, sB + aoffB + p * 16 * PITCH * 2 + ks * 32);
                #pragma unroll
                for (int mi = 0; mi < 2; mi++) {
                    mma16816(acc[mi][2*p],   af[mi], bf4[0], bf4[1]);
                    mma16816(acc[mi][2*p+1], af[mi], bf4[2], bf4[3]);
                }
            }
        }

        if (kt + 2 < KT) {
            const int ns = (stg + 2 >= 3) ? stg - 1 : stg + 2;
            G_ISSUE(kt + 2, ns); cpcommit();
        }
        stg = (stg + 1 == 3) ? 0 : stg + 1;
    }
    #undef G_ISSUE

    const int r0 = bm + wm + (lane >> 2);
    const int cb = bn + wn + (lane & 3) * 2;
    #pragma unroll
    for (int mi = 0; mi < 2; mi++) {
        #pragma unroll
        for (int j = 0; j < 8; j++) {
            const int col = cb + j * 8;
            const float b0v = bias[col], b1v = bias[col + 1];
            const int ra = r0 + mi * 16, rb = ra + 8;
            float2 v0 = { acc[mi][j][0] + b0v, acc[mi][j][1] + b1v };
            float2 v1 = { acc[mi][j][2] + b0v, acc[mi][j][3] + b1v };
            if (EPI == 1) {
                const float2 ra2 = *reinterpret_cast<const float2*>(
                    res + (size_t)ra * Nn + col);
                const float2 rb2 = *reinterpret_cast<const float2*>(
                    res + (size_t)rb * Nn + col);
                v0.x += ra2.x; v0.y += ra2.y; v1.x += rb2.x; v1.y += rb2.y;
            }
            if (EPI == 2) {
                *reinterpret_cast<uint32_t*>(Ch + (size_t)ra * Nn + col) =
                    pckf(gelu_exact(v0.x), gelu_exact(v0.y));
                *reinterpret_cast<uint32_t*>(Ch + (size_t)rb * Nn + col) =
                    pckf(gelu_exact(v1.x), gelu_exact(v1.y));
            } else if (EPI == 3) {
                *reinterpret_cast<uint32_t*>(Ch + (size_t)ra * Nn + col) =
                    pckf(v0.x, v0.y);
                *reinterpret_cast<uint32_t*>(Ch + (size_t)rb * Nn + col) =
                    pckf(v1.x, v1.y);
            } else {
                *reinterpret_cast<float2*>(Co + (size_t)ra * Nn + col) = v0;
                *reinterpret_cast<float2*>(Co + (size_t)rb * Nn + col) = v1;
            }
        }
    }
}

// ---------------- flash attention v4: 3-stage KV, f16x2 softmax -------------
#define APITCH 72
#define ATILE  (64 * APITCH * 2)        // 9216 B
#define QTILE  (128 * APITCH * 2)       // 18432 B
#define ASMEM  (QTILE + 3 * 2 * ATILE)  // 73728 B

__global__ __launch_bounds__(256) void flash_attn4_kernel(
    const __half* __restrict__ q, const __half* __restrict__ k,
    const __half* __restrict__ v, __half* __restrict__ o)
{
    extern __shared__ char shm[];
    const uint32_t sbase = smem_u32(shm);
    const uint32_t kvb0  = sbase + QTILE;

    const int t    = threadIdx.x;
    const int lane = t & 31;
    const int warp = t >> 5;
    const int b    = blockIdx.y >> 4;
    const int h    = blockIdx.y & 15;
    const int q0   = blockIdx.x * 128;
    const int wm   = warp * 16;

    #pragma unroll
    for (int i = 0; i < 4; i++) {
        const int idx = i * 256 + t;
        const int row = idx >> 3, c = idx & 7;
        cp16(sbase + row * (APITCH * 2) + c * 16,
             q + (size_t)(b * NSEQ + q0 + row) * CDIM + h * HDIM + c * 8);
    }
    cpcommit();

    #define KV_ISSUE(kt, stg)                                                 \
        { const uint32_t sb = kvb0 + (uint32_t)(stg) * 2 * ATILE;             \
          _Pragma("unroll")                                                   \
          for (int i = 0; i < 2; i++) {                                       \
              const int idx = i * 256 + t;                                    \
              const int row = idx >> 3, c = idx & 7;                          \
              const size_t g = (size_t)(b * NSEQ + (kt) * 64 + row) * CDIM    \
                               + h * HDIM + c * 8;                            \
              const uint32_t d = sb + row * (APITCH * 2) + c * 16;            \
              cp16(d,         k + g);                                         \
              cp16(d + ATILE, v + g);                                         \
          } }

    KV_ISSUE(0, 0); cpcommit();
    KV_ISSUE(1, 1); cpcommit();
    cpwait2();                       // Q ready
    __syncthreads();

    uint32_t qf[4][4];
    #pragma unroll
    for (int ks = 0; ks < 4; ks++)
        ldmat4(qf[ks], sbase + ((wm + (lane & 15)) * APITCH + ks * 16
                                + (lane >> 4) * 8) * 2);

    float m0 = -1e30f, m1 = -1e30f, l0 = 0.0f, l1 = 0.0f;
    float oa[8][4];
    #pragma unroll
    for (int j = 0; j < 8; j++)
        #pragma unroll
        for (int p = 0; p < 4; p++) oa[j][p] = 0.0f;

    const uint32_t one2 = 0x3C003C00u;   // fp16 (1.0, 1.0)
    const int NT = NSEQ / 64;
    int stg = 0;
    for (int kt = 0; kt < NT; kt++) {
        if (kt + 1 < NT) cpwait1(); else cpwait0();
        __syncthreads();

        const uint32_t kb = kvb0 + (uint32_t)stg * 2 * ATILE;
        const uint32_t vb = kb + ATILE;

        float sc[8][4];
        #pragma unroll
        for (int j = 0; j < 8; j++)
            #pragma unroll
            for (int p = 0; p < 4; p++) sc[j][p] = 0.0f;

        #pragma unroll
        for (int ks = 0; ks < 4; ks++) {
            #pragma unroll
            for (int p = 0; p < 4; p++) {
                uint32_t r4[4];
                ldmat4(r4, kb + ((p * 16 + (lane & 7) + ((lane >> 4) << 3)) * APITCH
                                 + ks * 16 + ((lane >> 3) & 1) * 8) * 2);
                mma16816(sc[2*p],   qf[ks], r4[0], r4[1]);
                mma16816(sc[2*p+1], qf[ks], r4[2], r4[3]);
            }
        }

        float mx0 = sc[0][0], mx1 = sc[0][2];
        #pragma unroll
        for (int j = 0; j < 8; j++) {
            mx0 = fmaxf(mx0, fmaxf(sc[j][0], sc[j][1]));
            mx1 = fmaxf(mx1, fmaxf(sc[j][2], sc[j][3]));
        }
        mx0 = fmaxf(mx0, __shfl_xor_sync(0xffffffffu, mx0, 1));
        mx0 = fmaxf(mx0, __shfl_xor_sync(0xffffffffu, mx0, 2));
        mx1 = fmaxf(mx1, __shfl_xor_sync(0xffffffffu, mx1, 1));
        mx1 = fmaxf(mx1, __shfl_xor_sync(0xffffffffu, mx1, 2));

        const float mn0 = fmaxf(m0, mx0), mn1 = fmaxf(m1, mx1);
        const float cr0 = ex2f(m0 - mn0), cr1 = ex2f(m1 - mn1);
        m0 = mn0; m1 = mn1;

        uint32_t pf[4][4];
        #pragma unroll
        for (int j = 0; j < 8; j++) {
            const float d0 = sc[j][0] - mn0;
            const float d1 = sc[j][1] - mn0;
            const float d2 = sc[j][2] - mn1;
            const float d3 = sc[j][3] - mn1;
            uint32_t c01, c23;
            asm("cvt.rn.f16x2.f32 %0, %1, %2;" : "=r"(c01) : "f"(d1), "f"(d0));
            asm("cvt.rn.f16x2.f32 %0, %1, %2;" : "=r"(c23) : "f"(d3), "f"(d2));
            uint32_t p01, p23;
            asm("ex2.approx.f16x2 %0, %1;" : "=r"(p01) : "r"(c01));
            asm("ex2.approx.f16x2 %0, %1;" : "=r"(p23) : "r"(c23));
            pf[j >> 1][(j & 1) * 2 + 0] = p01;
            pf[j >> 1][(j & 1) * 2 + 1] = p23;
        }

        // row sums via HMMA against ones
        float ls[4] = {0.0f, 0.0f, 0.0f, 0.0f};
        #pragma unroll
        for (int ks = 0; ks < 4; ks++) mma16816(ls, pf[ks], one2, one2);
        l0 = l0 * cr0 + ls[0];
        l1 = l1 * cr1 + ls[2];

        #pragma unroll
        for (int j = 0; j < 8; j++) {
            oa[j][0] *= cr0; oa[j][1] *= cr0;
            oa[j][2] *= cr1; oa[j][3] *= cr1;
        }

        #pragma unroll
        for (int ks = 0; ks < 4; ks++) {
            #pragma unroll
            for (int p = 0; p < 4; p++) {
                uint32_t r4[4];
                ldmat4t(r4, vb + ((ks * 16 + (lane & 15)) * APITCH
                                  + p * 16 + ((lane >> 4) << 3)) * 2);
                mma16816(oa[2*p],   pf[ks], r4[0], r4[1]);
                mma16816(oa[2*p+1], pf[ks], r4[2], r4[3]);
            }
        }

        if (kt + 2 < NT) {
            const int ns = (stg + 2 >= 3) ? stg - 1 : stg + 2;
            KV_ISSUE(kt + 2, ns); cpcommit();
        }
        stg = (stg + 1 == 3) ? 0 : stg + 1;
    }
    #undef KV_ISSUE

    const float iv0 = 1.0f / l0, iv1 = 1.0f / l1;
    const int ra = q0 + wm + (lane >> 2);
    const int rb = ra + 8;
    #pragma unroll
    for (int j = 0; j < 8; j++) {
        const int col = h * HDIM + j * 8 + (lane & 3) * 2;
        *reinterpret_cast<uint32_t*>(o + (size_t)(b * NSEQ + ra) * CDIM + col) =
            pckf(oa[j][0] * iv0, oa[j][1] * iv0);
        *reinterpret_cast<uint32_t*>(o + (size_t)(b * NSEQ + rb) * CDIM + col) =
            pckf(oa[j][2] * iv1, oa[j][3] * iv1);
    }
}

// ---------------- host orchestration ----------------------------------------
extern "C" void kernel_launch(void* const* d_in, const int* in_sizes, int n_in,
                              void* d_out, int out_size)
{
    const float* x      = (const float*)d_in[0];
    const float* wq     = (const float*)d_in[1];
    const float* bq     = (const float*)d_in[2];
    const float* wk     = (const float*)d_in[3];
    const float* bk     = (const float*)d_in[4];
    const float* wv     = (const float*)d_in[5];
    const float* bv     = (const float*)d_in[6];
    const float* wo     = (const float*)d_in[7];
    const float* bo     = (const float*)d_in[8];
    const float* scale1 = (const float*)d_in[9];
    const float* scale2 = (const float*)d_in[10];
    const float* w1     = (const float*)d_in[11];
    const float* b1     = (const float*)d_in[12];
    const float* w2     = (const float*)d_in[13];
    const float* b2     = (const float*)d_in[14];
    float* out = (float*)d_out;

    __half *p_xn, *p_qkvh, *p_qb, *p_kb, *p_vb, *p_ctx, *p_xn2, *p_h;
    __half *p_wqkv, *p_wo, *p_w1, *p_w2;
    float *p_x2, *p_bqkv;
    cudaGetSymbolAddress((void**)&p_xn,   g_xn);
    cudaGetSymbolAddress((void**)&p_qkvh, g_qkvh);
    cudaGetSymbolAddress((void**)&p_qb,   g_qb);
    cudaGetSymbolAddress((void**)&p_kb,   g_kb);
    cudaGetSymbolAddress((void**)&p_vb,   g_vb);
    cudaGetSymbolAddress((void**)&p_ctx,  g_ctx);
    cudaGetSymbolAddress((void**)&p_x2,   g_x2);
    cudaGetSymbolAddress((void**)&p_xn2,  g_xn2);
    cudaGetSymbolAddress((void**)&p_h,    g_h);
    cudaGetSymbolAddress((void**)&p_wqkv, g_wqkv);
    cudaGetSymbolAddress((void**)&p_wo,   g_wo);
    cudaGetSymbolAddress((void**)&p_w1,   g_w1);
    cudaGetSymbolAddress((void**)&p_w2,   g_w2);
    cudaGetSymbolAddress((void**)&p_bqkv, g_bqkv);

    cudaFuncSetAttribute(gemm4_kernel<0>,
                         cudaFuncAttributeMaxDynamicSharedMemorySize, GSMEM);
    cudaFuncSetAttribute(gemm4_kernel<1>,
                         cudaFuncAttributeMaxDynamicSharedMemorySize, GSMEM);
    cudaFuncSetAttribute(gemm4_kernel<2>,
                         cudaFuncAttributeMaxDynamicSharedMemorySize, GSMEM);
    cudaFuncSetAttribute(gemm4_kernel<3>,
                         cudaFuncAttributeMaxDynamicSharedMemorySize, GSMEM);
    cudaFuncSetAttribute(flash_attn4_kernel,
                         cudaFuncAttributeMaxDynamicSharedMemorySize, ASMEM);

    const dim3 tb(32, 8);

    bias_concat_kernel<<<QKVN / 256, 256>>>(bq, bk, bv, p_bqkv);
    transpose_h_kernel<<<dim3(CDIM/32, CDIM/32), tb>>>(wq, p_wqkv, CDIM, CDIM);
    transpose_h_kernel<<<dim3(CDIM/32, CDIM/32), tb>>>(
        wk, p_wqkv + (size_t)CDIM*CDIM, CDIM, CDIM);
    transpose_h_kernel<<<dim3(CDIM/32, CDIM/32), tb>>>(
        wv, p_wqkv + (size_t)2*CDIM*CDIM, CDIM, CDIM);
    rmsnorm_h_kernel<<<MTOT, 256>>>(x, scale1, p_xn);
    // fused QKV GEMM -> fp16
    gemm4_kernel<3><<<dim3(QKVN/128, MTOT/128), 256, GSMEM>>>(
        p_xn, p_wqkv, p_bqkv, nullptr, nullptr, p_qkvh, MTOT, QKVN, CDIM);
    postqkv_kernel<<<dim3(MTOT*NHEAD/256, 3), 256>>>(p_qkvh, p_qb, p_kb, p_vb);
    flash_attn4_kernel<<<dim3(NSEQ/128, 2*NHEAD), 256, ASMEM>>>(
        p_qb, p_kb, p_vb, p_ctx);
    transpose_h_kernel<<<dim3(CDIM/32, CDIM/32), tb>>>(wo, p_wo, CDIM, CDIM);
    gemm4_kernel<1><<<dim3(CDIM/128, MTOT/128), 256, GSMEM>>>(
        p_ctx, p_wo, bo, x, p_x2, nullptr, MTOT, CDIM, CDIM);
    rmsnorm_h_kernel<<<MTOT, 256>>>(p_x2, scale2, p_xn2);
    transpose_h_kernel<<<dim3(FFDIM/32, CDIM/32), tb>>>(w1, p_w1, CDIM, FFDIM);
    gemm4_kernel<2><<<dim3(FFDIM/128, MTOT/128), 256, GSMEM>>>(
        p_xn2, p_w1, b1, nullptr, nullptr, p_h, MTOT, FFDIM, CDIM);
    transpose_h_kernel<<<dim3(CDIM/32, FFDIM/32), tb>>>(w2, p_w2, FFDIM, CDIM);
    gemm4_kernel<1><<<dim3(CDIM/128, MTOT/128), 256, GSMEM>>>(
        p_h, p_w2, b2, p_x2, out, nullptr, MTOT, CDIM, FFDIM);
}